// round 1
// baseline (speedup 1.0000x reference)
#include <cuda_runtime.h>
#include <cuda_bf16.h>
#include <cstdint>

#define NNODES 50000
#define NEDGES 800000
#define C1 256            // heads*hid layer1
#define C2 128            // out channels layer2
#define NEG_SLOPE 0.2f
#define EPS_DEN 1e-16f

// ---------------- scratch (device globals; no allocations allowed) ----------------
__device__ float    g_xl1[NNODES * C1];
__device__ float    g_xr1[NNODES * C1];
__device__ float    g_h  [NNODES * C1];   // layer1 aggregation -> ELU -> layer2 input
__device__ float    g_hl2[NNODES * C2];
__device__ float    g_hr2[NNODES * C2];
__device__ float    g_e1 [NEDGES * 4];
__device__ float    g_e2 [NEDGES];
__device__ unsigned g_emax1[NNODES * 4];
__device__ unsigned g_emax2[NNODES];
__device__ float    g_den1[NNODES * 4];
__device__ float    g_den2[NNODES];

// ---------------- helpers ----------------
__device__ __forceinline__ float lrelu(float x) { return x > 0.f ? x : NEG_SLOPE * x; }

// order-preserving float<->uint mapping for atomicMax
__device__ __forceinline__ unsigned fenc(float f) {
    unsigned u = __float_as_uint(f);
    return (u & 0x80000000u) ? ~u : (u | 0x80000000u);
}
__device__ __forceinline__ float fdec(unsigned u) {
    unsigned v = (u & 0x80000000u) ? (u & 0x7fffffffu) : ~u;
    return __uint_as_float(v);
}

__device__ __forceinline__ void red_add_v4(float* ptr, float a, float b, float c, float d) {
    asm volatile("red.global.add.v4.f32 [%0], {%1,%2,%3,%4};"
                 :: "l"(ptr), "f"(a), "f"(b), "f"(c), "f"(d) : "memory");
}

// ---------------- init: zero softmax stats, seed biases ----------------
__global__ void k_setup(const float* __restrict__ b1, const float* __restrict__ b2,
                        float* __restrict__ out) {
    int i = blockIdx.x * blockDim.x + threadIdx.x;
    if (i < NNODES * C1) g_h[i] = b1[i & (C1 - 1)];
    if (i < NNODES * C2) out[i] = b2[i & (C2 - 1)];
    if (i < NNODES * 4) { g_emax1[i] = 0u; g_den1[i] = 0.f; }
    if (i < NNODES)     { g_emax2[i] = 0u; g_den2[i] = 0.f; }
}

// ---------------- SGEMM: C[M,Nn] = A[M,K] @ B[K,Nn], row-major ----------------
// BM=BN=128, BK=8, 256 threads, 8x8 per-thread tile. Nn % 128 == 0, K % 8 == 0.
__global__ __launch_bounds__(256) void sgemm128(const float* __restrict__ A,
                                                const float* __restrict__ B,
                                                float* __restrict__ C,
                                                int M, int Nn, int K) {
    __shared__ float As[8][128];
    __shared__ float Bs[8][128];
    const int tid  = threadIdx.x;
    const int brow = blockIdx.x * 128;
    const int bcol = blockIdx.y * 128;
    const int trow = (tid >> 4) * 8;
    const int tcol = (tid & 15) * 8;
    const int aRow = tid >> 1;
    const int aCol = (tid & 1) * 4;
    const int bRow = tid >> 5;
    const int bCol = (tid & 31) * 4;

    float acc[8][8];
#pragma unroll
    for (int i = 0; i < 8; i++)
#pragma unroll
        for (int j = 0; j < 8; j++) acc[i][j] = 0.f;

    for (int k0 = 0; k0 < K; k0 += 8) {
        float4 av = make_float4(0.f, 0.f, 0.f, 0.f);
        int gr = brow + aRow;
        if (gr < M) av = *(const float4*)(A + (size_t)gr * K + k0 + aCol);
        As[aCol + 0][aRow] = av.x;
        As[aCol + 1][aRow] = av.y;
        As[aCol + 2][aRow] = av.z;
        As[aCol + 3][aRow] = av.w;
        *(float4*)&Bs[bRow][bCol] =
            *(const float4*)(B + (size_t)(k0 + bRow) * Nn + bcol + bCol);
        __syncthreads();
#pragma unroll
        for (int kk = 0; kk < 8; kk++) {
            float ar[8], br[8];
#pragma unroll
            for (int i = 0; i < 8; i++) ar[i] = As[kk][trow + i];
#pragma unroll
            for (int j = 0; j < 8; j++) br[j] = Bs[kk][tcol + j];
#pragma unroll
            for (int i = 0; i < 8; i++)
#pragma unroll
                for (int j = 0; j < 8; j++) acc[i][j] = fmaf(ar[i], br[j], acc[i][j]);
        }
        __syncthreads();
    }
#pragma unroll
    for (int i = 0; i < 8; i++) {
        int row = brow + trow + i;
        if (row < M) {
            float4* p = (float4*)(C + (size_t)row * Nn + bcol + tcol);
            p[0] = make_float4(acc[i][0], acc[i][1], acc[i][2], acc[i][3]);
            p[1] = make_float4(acc[i][4], acc[i][5], acc[i][6], acc[i][7]);
        }
    }
}

// ---------------- layer 1 edge kernels (H=4, C=64, per-node feat 256) ----------------
// one warp per edge; lane handles 8 channels, head = lane>>3
__global__ __launch_bounds__(256) void edge_logits1(const int* __restrict__ ei,
                                                    const float* __restrict__ att) {
    int e = blockIdx.x * 8 + (threadIdx.x >> 5);
    if (e >= NEDGES) return;
    int lane = threadIdx.x & 31;
    int src = ei[e], dst = ei[NEDGES + e];
    int base = lane * 8;
    const float4* pl = (const float4*)(g_xl1 + (size_t)src * C1 + base);
    const float4* pr = (const float4*)(g_xr1 + (size_t)dst * C1 + base);
    const float4* pa = (const float4*)(att + base);
    float4 a0 = pl[0], a1 = pl[1];
    float4 b0 = pr[0], b1 = pr[1];
    float4 t0 = pa[0], t1 = pa[1];
    float s = lrelu(a0.x + b0.x) * t0.x + lrelu(a0.y + b0.y) * t0.y +
              lrelu(a0.z + b0.z) * t0.z + lrelu(a0.w + b0.w) * t0.w +
              lrelu(a1.x + b1.x) * t1.x + lrelu(a1.y + b1.y) * t1.y +
              lrelu(a1.z + b1.z) * t1.z + lrelu(a1.w + b1.w) * t1.w;
    s += __shfl_xor_sync(0xffffffffu, s, 1);
    s += __shfl_xor_sync(0xffffffffu, s, 2);
    s += __shfl_xor_sync(0xffffffffu, s, 4);
    if ((lane & 7) == 0) {
        int h = lane >> 3;
        g_e1[(size_t)e * 4 + h] = s;
        atomicMax(&g_emax1[dst * 4 + h], fenc(s));
    }
}

// one thread per (edge, head)
__global__ __launch_bounds__(256) void edge_exp1(const int* __restrict__ ei) {
    int idx = blockIdx.x * blockDim.x + threadIdx.x;
    if (idx >= NEDGES * 4) return;
    int e = idx >> 2, h = idx & 3;
    int dst = ei[NEDGES + e];
    float m = fdec(g_emax1[dst * 4 + h]);
    float ee = __expf(g_e1[idx] - m);
    g_e1[idx] = ee;
    atomicAdd(&g_den1[dst * 4 + h], ee);
}

// one warp per edge, lane handles 8 channels; scatter into g_h with red.v4
__global__ __launch_bounds__(256) void edge_aggr1(const int* __restrict__ ei) {
    int e = blockIdx.x * 8 + (threadIdx.x >> 5);
    if (e >= NEDGES) return;
    int lane = threadIdx.x & 31;
    int src = ei[e], dst = ei[NEDGES + e];
    int h = lane >> 3;
    float alpha = g_e1[(size_t)e * 4 + h] / (g_den1[dst * 4 + h] + EPS_DEN);
    int base = lane * 8;
    const float4* pl = (const float4*)(g_xl1 + (size_t)src * C1 + base);
    float4 a0 = pl[0], a1 = pl[1];
    float* po = g_h + (size_t)dst * C1 + base;
    red_add_v4(po,     alpha * a0.x, alpha * a0.y, alpha * a0.z, alpha * a0.w);
    red_add_v4(po + 4, alpha * a1.x, alpha * a1.y, alpha * a1.z, alpha * a1.w);
}

__global__ void k_elu() {
    int i = blockIdx.x * blockDim.x + threadIdx.x;
    if (i < NNODES * C1) {
        float v = g_h[i];
        g_h[i] = v > 0.f ? v : expm1f(v);
    }
}

// ---------------- layer 2 edge kernels (H=1, C=128) ----------------
__global__ __launch_bounds__(256) void edge_logits2(const int* __restrict__ ei,
                                                    const float* __restrict__ att) {
    int e = blockIdx.x * 8 + (threadIdx.x >> 5);
    if (e >= NEDGES) return;
    int lane = threadIdx.x & 31;
    int src = ei[e], dst = ei[NEDGES + e];
    int base = lane * 4;
    float4 a = *(const float4*)(g_hl2 + (size_t)src * C2 + base);
    float4 b = *(const float4*)(g_hr2 + (size_t)dst * C2 + base);
    float4 t = *(const float4*)(att + base);
    float s = lrelu(a.x + b.x) * t.x + lrelu(a.y + b.y) * t.y +
              lrelu(a.z + b.z) * t.z + lrelu(a.w + b.w) * t.w;
#pragma unroll
    for (int d = 16; d >= 1; d >>= 1) s += __shfl_xor_sync(0xffffffffu, s, d);
    if (lane == 0) {
        g_e2[e] = s;
        atomicMax(&g_emax2[dst], fenc(s));
    }
}

__global__ __launch_bounds__(256) void edge_exp2(const int* __restrict__ ei) {
    int e = blockIdx.x * blockDim.x + threadIdx.x;
    if (e >= NEDGES) return;
    int dst = ei[NEDGES + e];
    float m = fdec(g_emax2[dst]);
    float ee = __expf(g_e2[e] - m);
    g_e2[e] = ee;
    atomicAdd(&g_den2[dst], ee);
}

__global__ __launch_bounds__(256) void edge_aggr2(const int* __restrict__ ei,
                                                  float* __restrict__ out) {
    int e = blockIdx.x * 8 + (threadIdx.x >> 5);
    if (e >= NEDGES) return;
    int lane = threadIdx.x & 31;
    int src = ei[e], dst = ei[NEDGES + e];
    float alpha = g_e2[e] / (g_den2[dst] + EPS_DEN);
    int base = lane * 4;
    float4 a = *(const float4*)(g_hl2 + (size_t)src * C2 + base);
    red_add_v4(out + (size_t)dst * C2 + base,
               alpha * a.x, alpha * a.y, alpha * a.z, alpha * a.w);
}

// ---------------- launch ----------------
extern "C" void kernel_launch(void* const* d_in, const int* in_sizes, int n_in,
                              void* d_out, int out_size) {
    const float* x    = (const float*)d_in[0];
    const int*   ei   = (const int*)d_in[1];
    const float* Wl1  = (const float*)d_in[2];
    const float* Wr1  = (const float*)d_in[3];
    const float* att1 = (const float*)d_in[4];
    const float* b1   = (const float*)d_in[5];
    const float* Wl2  = (const float*)d_in[6];
    const float* Wr2  = (const float*)d_in[7];
    const float* att2 = (const float*)d_in[8];
    const float* b2   = (const float*)d_in[9];
    float* out = (float*)d_out;

    float *xl1, *xr1, *h, *hl2, *hr2;
    cudaGetSymbolAddress((void**)&xl1, g_xl1);
    cudaGetSymbolAddress((void**)&xr1, g_xr1);
    cudaGetSymbolAddress((void**)&h,   g_h);
    cudaGetSymbolAddress((void**)&hl2, g_hl2);
    cudaGetSymbolAddress((void**)&hr2, g_hr2);

    const int T = 256;
    // init
    k_setup<<<(NNODES * C1 + T - 1) / T, T>>>(b1, b2, out);

    // layer 1 projections: [N,128] @ [128,256]
    {
        dim3 grid((NNODES + 127) / 128, C1 / 128);
        sgemm128<<<grid, 256>>>(x, Wl1, xl1, NNODES, C1, 128);
        sgemm128<<<grid, 256>>>(x, Wr1, xr1, NNODES, C1, 128);
    }
    int eblk = (NEDGES + 7) / 8;
    edge_logits1<<<eblk, 256>>>(ei, att1);
    edge_exp1<<<(NEDGES * 4 + T - 1) / T, T>>>(ei);
    edge_aggr1<<<eblk, 256>>>(ei);
    k_elu<<<(NNODES * C1 + T - 1) / T, T>>>();

    // layer 2 projections: [N,256] @ [256,128]
    {
        dim3 grid((NNODES + 127) / 128, C2 / 128);
        sgemm128<<<grid, 256>>>(h, Wl2, hl2, NNODES, C2, 256);
        sgemm128<<<grid, 256>>>(h, Wr2, hr2, NNODES, C2, 256);
    }
    edge_logits2<<<eblk, 256>>>(ei, att2);
    edge_exp2<<<(NEDGES + T - 1) / T, T>>>(ei);
    edge_aggr2<<<eblk, 256>>>(ei, out);
}

// round 2
// speedup vs baseline: 1.1808x; 1.1808x over previous
#include <cuda_runtime.h>
#include <cuda_bf16.h>
#include <cstdint>

#define NNODES 50000
#define NEDGES 800000
#define C1 256            // heads*hid layer1
#define C2 128            // out channels layer2
#define NEG_SLOPE 0.2f
#define EPS_DEN 1e-16f

// ---------------- scratch (device globals; no allocations allowed) ----------------
__device__ float g_xl1[NNODES * C1];
__device__ float g_xr1[NNODES * C1];
__device__ float g_h  [NNODES * C1];   // layer1 numerator accum -> finalize -> layer2 input
__device__ float g_hl2[NNODES * C2];
__device__ float g_hr2[NNODES * C2];
__device__ float g_den1[NNODES * 4];
__device__ float g_den2[NNODES];

// ---------------- helpers ----------------
__device__ __forceinline__ float lrelu(float x) { return x > 0.f ? x : NEG_SLOPE * x; }

__device__ __forceinline__ void red_add_v4(float* ptr, float a, float b, float c, float d) {
    asm volatile("red.global.add.v4.f32 [%0], {%1,%2,%3,%4};"
                 :: "l"(ptr), "f"(a), "f"(b), "f"(c), "f"(d) : "memory");
}

// ---------------- init: zero accumulators ----------------
__global__ void k_init(float* __restrict__ out) {
    int i = blockIdx.x * blockDim.x + threadIdx.x;
    if (i < NNODES * C1) g_h[i] = 0.f;
    if (i < NNODES * C2) out[i] = 0.f;
    if (i < NNODES * 4)  g_den1[i] = 0.f;
    if (i < NNODES)      g_den2[i] = 0.f;
}

// ---------------- SGEMM: C[M,Nn] = A[M,K] @ B[K,Nn], row-major ----------------
// BM=BN=128, BK=8, 256 threads, 8x8 per-thread tile. Nn % 128 == 0, K % 8 == 0.
__global__ __launch_bounds__(256) void sgemm128(const float* __restrict__ A,
                                                const float* __restrict__ B,
                                                float* __restrict__ C,
                                                int M, int Nn, int K) {
    __shared__ float As[8][128];
    __shared__ float Bs[8][128];
    const int tid  = threadIdx.x;
    const int brow = blockIdx.x * 128;
    const int bcol = blockIdx.y * 128;
    const int trow = (tid >> 4) * 8;
    const int tcol = (tid & 15) * 8;
    const int aRow = tid >> 1;
    const int aCol = (tid & 1) * 4;
    const int bRow = tid >> 5;
    const int bCol = (tid & 31) * 4;

    float acc[8][8];
#pragma unroll
    for (int i = 0; i < 8; i++)
#pragma unroll
        for (int j = 0; j < 8; j++) acc[i][j] = 0.f;

    for (int k0 = 0; k0 < K; k0 += 8) {
        float4 av = make_float4(0.f, 0.f, 0.f, 0.f);
        int gr = brow + aRow;
        if (gr < M) av = *(const float4*)(A + (size_t)gr * K + k0 + aCol);
        As[aCol + 0][aRow] = av.x;
        As[aCol + 1][aRow] = av.y;
        As[aCol + 2][aRow] = av.z;
        As[aCol + 3][aRow] = av.w;
        *(float4*)&Bs[bRow][bCol] =
            *(const float4*)(B + (size_t)(k0 + bRow) * Nn + bcol + bCol);
        __syncthreads();
#pragma unroll
        for (int kk = 0; kk < 8; kk++) {
            float ar[8], br[8];
#pragma unroll
            for (int i = 0; i < 8; i++) ar[i] = As[kk][trow + i];
#pragma unroll
            for (int j = 0; j < 8; j++) br[j] = Bs[kk][tcol + j];
#pragma unroll
            for (int i = 0; i < 8; i++)
#pragma unroll
                for (int j = 0; j < 8; j++) acc[i][j] = fmaf(ar[i], br[j], acc[i][j]);
        }
        __syncthreads();
    }
#pragma unroll
    for (int i = 0; i < 8; i++) {
        int row = brow + trow + i;
        if (row < M) {
            float4* p = (float4*)(C + (size_t)row * Nn + bcol + tcol);
            p[0] = make_float4(acc[i][0], acc[i][1], acc[i][2], acc[i][3]);
            p[1] = make_float4(acc[i][4], acc[i][5], acc[i][6], acc[i][7]);
        }
    }
}

// ---------------- layer 1 fused edge pass (H=4, C=64 per head) ----------------
// one warp per edge; lane handles 8 channels, head = lane>>3
// computes ee = exp(logit), scatters ee*xl into g_h and ee into g_den1
__global__ __launch_bounds__(256) void edge_fused1(const int* __restrict__ ei,
                                                   const float* __restrict__ att) {
    int e = blockIdx.x * 8 + (threadIdx.x >> 5);
    if (e >= NEDGES) return;
    int lane = threadIdx.x & 31;
    int src = ei[e], dst = ei[NEDGES + e];
    int base = lane * 8;
    const float4* pl = (const float4*)(g_xl1 + (size_t)src * C1 + base);
    const float4* pr = (const float4*)(g_xr1 + (size_t)dst * C1 + base);
    const float4* pa = (const float4*)(att + base);
    float4 a0 = pl[0], a1 = pl[1];
    float4 b0 = pr[0], b1 = pr[1];
    float4 t0 = pa[0], t1 = pa[1];
    float s = lrelu(a0.x + b0.x) * t0.x + lrelu(a0.y + b0.y) * t0.y +
              lrelu(a0.z + b0.z) * t0.z + lrelu(a0.w + b0.w) * t0.w +
              lrelu(a1.x + b1.x) * t1.x + lrelu(a1.y + b1.y) * t1.y +
              lrelu(a1.z + b1.z) * t1.z + lrelu(a1.w + b1.w) * t1.w;
    s += __shfl_xor_sync(0xffffffffu, s, 1);
    s += __shfl_xor_sync(0xffffffffu, s, 2);
    s += __shfl_xor_sync(0xffffffffu, s, 4);
    float ee = __expf(s);
    float* po = g_h + (size_t)dst * C1 + base;
    red_add_v4(po,     ee * a0.x, ee * a0.y, ee * a0.z, ee * a0.w);
    red_add_v4(po + 4, ee * a1.x, ee * a1.y, ee * a1.z, ee * a1.w);
    if ((lane & 7) == 0)
        atomicAdd(&g_den1[dst * 4 + (lane >> 3)], ee);
}

// finalize layer 1: h = ELU(num/(den+eps) + b1)
__global__ void k_fin1(const float* __restrict__ b1) {
    int i = blockIdx.x * blockDim.x + threadIdx.x;
    if (i >= NNODES * C1) return;
    int c = i & (C1 - 1);
    int node = i >> 8;
    float den = g_den1[node * 4 + (c >> 6)];
    float v = g_h[i] / (den + EPS_DEN) + b1[c];
    g_h[i] = v > 0.f ? v : expm1f(v);
}

// ---------------- layer 2 fused edge pass (H=1, C=128) ----------------
__global__ __launch_bounds__(256) void edge_fused2(const int* __restrict__ ei,
                                                   const float* __restrict__ att,
                                                   float* __restrict__ out) {
    int e = blockIdx.x * 8 + (threadIdx.x >> 5);
    if (e >= NEDGES) return;
    int lane = threadIdx.x & 31;
    int src = ei[e], dst = ei[NEDGES + e];
    int base = lane * 4;
    float4 a = *(const float4*)(g_hl2 + (size_t)src * C2 + base);
    float4 b = *(const float4*)(g_hr2 + (size_t)dst * C2 + base);
    float4 t = *(const float4*)(att + base);
    float s = lrelu(a.x + b.x) * t.x + lrelu(a.y + b.y) * t.y +
              lrelu(a.z + b.z) * t.z + lrelu(a.w + b.w) * t.w;
#pragma unroll
    for (int d = 16; d >= 1; d >>= 1) s += __shfl_xor_sync(0xffffffffu, s, d);
    float ee = __expf(s);
    red_add_v4(out + (size_t)dst * C2 + base,
               ee * a.x, ee * a.y, ee * a.z, ee * a.w);
    if (lane == 0)
        atomicAdd(&g_den2[dst], ee);
}

// finalize layer 2: out = num/(den+eps) + b2
__global__ void k_fin2(const float* __restrict__ b2, float* __restrict__ out) {
    int i = blockIdx.x * blockDim.x + threadIdx.x;
    if (i >= NNODES * C2) return;
    int c = i & (C2 - 1);
    int node = i >> 7;
    float den = g_den2[node];
    out[i] = out[i] / (den + EPS_DEN) + b2[c];
}

// ---------------- launch ----------------
extern "C" void kernel_launch(void* const* d_in, const int* in_sizes, int n_in,
                              void* d_out, int out_size) {
    const float* x    = (const float*)d_in[0];
    const int*   ei   = (const int*)d_in[1];
    const float* Wl1  = (const float*)d_in[2];
    const float* Wr1  = (const float*)d_in[3];
    const float* att1 = (const float*)d_in[4];
    const float* b1   = (const float*)d_in[5];
    const float* Wl2  = (const float*)d_in[6];
    const float* Wr2  = (const float*)d_in[7];
    const float* att2 = (const float*)d_in[8];
    const float* b2   = (const float*)d_in[9];
    float* out = (float*)d_out;

    float *xl1, *xr1, *h, *hl2, *hr2;
    cudaGetSymbolAddress((void**)&xl1, g_xl1);
    cudaGetSymbolAddress((void**)&xr1, g_xr1);
    cudaGetSymbolAddress((void**)&h,   g_h);
    cudaGetSymbolAddress((void**)&hl2, g_hl2);
    cudaGetSymbolAddress((void**)&hr2, g_hr2);

    const int T = 256;
    k_init<<<(NNODES * C1 + T - 1) / T, T>>>(out);

    // layer 1 projections: [N,128] @ [128,256]
    {
        dim3 grid((NNODES + 127) / 128, C1 / 128);
        sgemm128<<<grid, 256>>>(x, Wl1, xl1, NNODES, C1, 128);
        sgemm128<<<grid, 256>>>(x, Wr1, xr1, NNODES, C1, 128);
    }
    int eblk = (NEDGES + 7) / 8;
    edge_fused1<<<eblk, 256>>>(ei, att1);
    k_fin1<<<(NNODES * C1 + T - 1) / T, T>>>(b1);

    // layer 2 projections: [N,256] @ [256,128]
    {
        dim3 grid((NNODES + 127) / 128, C2 / 128);
        sgemm128<<<grid, 256>>>(h, Wl2, hl2, NNODES, C2, 256);
        sgemm128<<<grid, 256>>>(h, Wr2, hr2, NNODES, C2, 256);
    }
    edge_fused2<<<eblk, 256>>>(ei, att2, out);
    k_fin2<<<(NNODES * C2 + T - 1) / T, T>>>(b2, out);
}

// round 3
// speedup vs baseline: 1.4671x; 1.2425x over previous
#include <cuda_runtime.h>
#include <cuda_bf16.h>
#include <cstdint>

#define NNODES 50000
#define NEDGES 800000
#define C1 256            // heads*hid layer1
#define C2 128            // out channels layer2
#define NEG_SLOPE 0.2f
#define EPS_DEN 1e-16f

// ---------------- scratch (device globals; no allocations allowed) ----------------
__device__ float g_xl1[NNODES * C1];
__device__ float g_xr1[NNODES * C1];
__device__ float g_h  [NNODES * C1];   // layer1 output (finalized) -> layer2 input
__device__ float g_hl2[NNODES * C2];
__device__ float g_hr2[NNODES * C2];
__device__ int   g_row[NNODES + 1];    // CSR row offsets (by dst)
__device__ int   g_cnt[NNODES];        // histogram / fill cursor
__device__ int   g_srcs[NEDGES];       // src ids sorted by dst

// ---------------- helpers ----------------
__device__ __forceinline__ float lrelu(float x) { return x > 0.f ? x : NEG_SLOPE * x; }

__device__ __forceinline__ unsigned long long fma_f32x2(unsigned long long a,
                                                        unsigned long long b,
                                                        unsigned long long c) {
    unsigned long long d;
    asm("fma.rn.f32x2 %0, %1, %2, %3;" : "=l"(d) : "l"(a), "l"(b), "l"(c));
    return d;
}

// ---------------- CSR build ----------------
__global__ void k_zero() {
    int i = blockIdx.x * blockDim.x + threadIdx.x;
    if (i < NNODES) g_cnt[i] = 0;
}

__global__ void k_count(const int* __restrict__ ei) {
    int e = blockIdx.x * blockDim.x + threadIdx.x;
    if (e < NEDGES) atomicAdd(&g_cnt[ei[NEDGES + e]], 1);
}

// single-block exclusive scan over g_cnt -> g_row; also zeroes g_cnt for cursor reuse
__global__ __launch_bounds__(1024) void k_scan() {
    __shared__ int s[1024];
    __shared__ int carry_s;
    int t = threadIdx.x;
    if (t == 0) carry_s = 0;
    __syncthreads();
    for (int base = 0; base < NNODES; base += 4096) {
        int idx = base + t * 4;
        int v0 = (idx + 0 < NNODES) ? g_cnt[idx + 0] : 0;
        int v1 = (idx + 1 < NNODES) ? g_cnt[idx + 1] : 0;
        int v2 = (idx + 2 < NNODES) ? g_cnt[idx + 2] : 0;
        int v3 = (idx + 3 < NNODES) ? g_cnt[idx + 3] : 0;
        int tot = v0 + v1 + v2 + v3;
        s[t] = tot;
        __syncthreads();
        for (int off = 1; off < 1024; off <<= 1) {
            int x = (t >= off) ? s[t - off] : 0;
            __syncthreads();
            s[t] += x;
            __syncthreads();
        }
        int excl = carry_s + s[t] - tot;
        if (idx + 0 < NNODES) { g_row[idx + 0] = excl;                 g_cnt[idx + 0] = 0; }
        if (idx + 1 < NNODES) { g_row[idx + 1] = excl + v0;            g_cnt[idx + 1] = 0; }
        if (idx + 2 < NNODES) { g_row[idx + 2] = excl + v0 + v1;       g_cnt[idx + 2] = 0; }
        if (idx + 3 < NNODES) { g_row[idx + 3] = excl + v0 + v1 + v2;  g_cnt[idx + 3] = 0; }
        __syncthreads();
        if (t == 1023) carry_s += s[1023];
        __syncthreads();
    }
    if (t == 0) g_row[NNODES] = NEDGES;
}

__global__ void k_fill(const int* __restrict__ ei) {
    int e = blockIdx.x * blockDim.x + threadIdx.x;
    if (e >= NEDGES) return;
    int dst = ei[NEDGES + e];
    int pos = g_row[dst] + atomicAdd(&g_cnt[dst], 1);
    g_srcs[pos] = ei[e];
}

// ---------------- SGEMM: C[M,Nn] = A[M,K] @ B[K,Nn], row-major, f32x2 inner ----------
// BM=BN=128, BK=8, 256 threads, 8x8 per-thread tile. Nn % 128 == 0, K % 8 == 0.
__global__ __launch_bounds__(256) void sgemm128(const float* __restrict__ A,
                                                const float* __restrict__ B,
                                                float* __restrict__ C,
                                                int M, int Nn, int K) {
    __shared__ float2 As2[8][128];   // A value duplicated into both lanes
    __shared__ float  Bs[8][128];
    const int tid  = threadIdx.x;
    const int brow = blockIdx.x * 128;
    const int bcol = blockIdx.y * 128;
    const int trow = (tid >> 4) * 8;
    const int tcol = (tid & 15) * 8;
    const int aRow = tid >> 1;
    const int aCol = (tid & 1) * 4;
    const int bRow = tid >> 5;
    const int bCol = (tid & 31) * 4;

    unsigned long long acc2[8][4];
#pragma unroll
    for (int i = 0; i < 8; i++)
#pragma unroll
        for (int j = 0; j < 4; j++) acc2[i][j] = 0ull;

    for (int k0 = 0; k0 < K; k0 += 8) {
        float4 av = make_float4(0.f, 0.f, 0.f, 0.f);
        int gr = brow + aRow;
        if (gr < M) av = *(const float4*)(A + (size_t)gr * K + k0 + aCol);
        As2[aCol + 0][aRow] = make_float2(av.x, av.x);
        As2[aCol + 1][aRow] = make_float2(av.y, av.y);
        As2[aCol + 2][aRow] = make_float2(av.z, av.z);
        As2[aCol + 3][aRow] = make_float2(av.w, av.w);
        *(float4*)&Bs[bRow][bCol] =
            *(const float4*)(B + (size_t)(k0 + bRow) * Nn + bcol + bCol);
        __syncthreads();
#pragma unroll
        for (int kk = 0; kk < 8; kk++) {
            unsigned long long ar2[8], br2[4];
#pragma unroll
            for (int i = 0; i < 8; i++)
                ar2[i] = *(const unsigned long long*)&As2[kk][trow + i];
#pragma unroll
            for (int j = 0; j < 4; j++)
                br2[j] = *(const unsigned long long*)&Bs[kk][tcol + 2 * j];
#pragma unroll
            for (int i = 0; i < 8; i++)
#pragma unroll
                for (int j = 0; j < 4; j++)
                    acc2[i][j] = fma_f32x2(ar2[i], br2[j], acc2[i][j]);
        }
        __syncthreads();
    }
#pragma unroll
    for (int i = 0; i < 8; i++) {
        int row = brow + trow + i;
        if (row < M) {
            float2* p = (float2*)(C + (size_t)row * Nn + bcol + tcol);
#pragma unroll
            for (int j = 0; j < 4; j++)
                p[j] = *(float2*)&acc2[i][j];
        }
    }
}

// ---------------- layer 1 aggregation: one warp per dst node (H=4, C=64/head) ------
// lane handles channels [lane*8, lane*8+8), head = lane>>3
__global__ __launch_bounds__(256) void aggr1(const float* __restrict__ att,
                                             const float* __restrict__ b1) {
    int node = blockIdx.x * 8 + (threadIdx.x >> 5);
    if (node >= NNODES) return;
    int lane = threadIdx.x & 31;
    int beg = g_row[node], end = g_row[node + 1];
    int base = lane * 8;

    const float4* pr = (const float4*)(g_xr1 + (size_t)node * C1 + base);
    float4 r0 = pr[0], r1 = pr[1];
    const float4* pa = (const float4*)(att + base);
    float4 t0 = pa[0], t1 = pa[1];

    float acc[8];
#pragma unroll
    for (int j = 0; j < 8; j++) acc[j] = 0.f;
    float den = 0.f;

    for (int i = beg; i < end; i++) {
        int src = g_srcs[i];
        const float4* pl = (const float4*)(g_xl1 + (size_t)src * C1 + base);
        float4 a0 = pl[0], a1 = pl[1];
        float s = lrelu(a0.x + r0.x) * t0.x + lrelu(a0.y + r0.y) * t0.y +
                  lrelu(a0.z + r0.z) * t0.z + lrelu(a0.w + r0.w) * t0.w +
                  lrelu(a1.x + r1.x) * t1.x + lrelu(a1.y + r1.y) * t1.y +
                  lrelu(a1.z + r1.z) * t1.z + lrelu(a1.w + r1.w) * t1.w;
        s += __shfl_xor_sync(0xffffffffu, s, 1);
        s += __shfl_xor_sync(0xffffffffu, s, 2);
        s += __shfl_xor_sync(0xffffffffu, s, 4);
        float ee = __expf(s);
        acc[0] = fmaf(ee, a0.x, acc[0]);
        acc[1] = fmaf(ee, a0.y, acc[1]);
        acc[2] = fmaf(ee, a0.z, acc[2]);
        acc[3] = fmaf(ee, a0.w, acc[3]);
        acc[4] = fmaf(ee, a1.x, acc[4]);
        acc[5] = fmaf(ee, a1.y, acc[5]);
        acc[6] = fmaf(ee, a1.z, acc[6]);
        acc[7] = fmaf(ee, a1.w, acc[7]);
        den += ee;
    }
    float inv = 1.f / (den + EPS_DEN);
    const float4* pb = (const float4*)(b1 + base);
    float4 bb0 = pb[0], bb1 = pb[1];
    float o[8];
    o[0] = acc[0] * inv + bb0.x;  o[1] = acc[1] * inv + bb0.y;
    o[2] = acc[2] * inv + bb0.z;  o[3] = acc[3] * inv + bb0.w;
    o[4] = acc[4] * inv + bb1.x;  o[5] = acc[5] * inv + bb1.y;
    o[6] = acc[6] * inv + bb1.z;  o[7] = acc[7] * inv + bb1.w;
#pragma unroll
    for (int j = 0; j < 8; j++) o[j] = o[j] > 0.f ? o[j] : expm1f(o[j]);
    float4* po = (float4*)(g_h + (size_t)node * C1 + base);
    po[0] = make_float4(o[0], o[1], o[2], o[3]);
    po[1] = make_float4(o[4], o[5], o[6], o[7]);
}

// ---------------- layer 2 aggregation: one warp per dst node (H=1, C=128) ----------
__global__ __launch_bounds__(256) void aggr2(const float* __restrict__ att,
                                             const float* __restrict__ b2,
                                             float* __restrict__ out) {
    int node = blockIdx.x * 8 + (threadIdx.x >> 5);
    if (node >= NNODES) return;
    int lane = threadIdx.x & 31;
    int beg = g_row[node], end = g_row[node + 1];
    int base = lane * 4;

    float4 r = *(const float4*)(g_hr2 + (size_t)node * C2 + base);
    float4 t = *(const float4*)(att + base);

    float4 acc = make_float4(0.f, 0.f, 0.f, 0.f);
    float den = 0.f;

    for (int i = beg; i < end; i++) {
        int src = g_srcs[i];
        float4 a = *(const float4*)(g_hl2 + (size_t)src * C2 + base);
        float s = lrelu(a.x + r.x) * t.x + lrelu(a.y + r.y) * t.y +
                  lrelu(a.z + r.z) * t.z + lrelu(a.w + r.w) * t.w;
#pragma unroll
        for (int d = 16; d >= 1; d >>= 1) s += __shfl_xor_sync(0xffffffffu, s, d);
        float ee = __expf(s);
        acc.x = fmaf(ee, a.x, acc.x);
        acc.y = fmaf(ee, a.y, acc.y);
        acc.z = fmaf(ee, a.z, acc.z);
        acc.w = fmaf(ee, a.w, acc.w);
        den += ee;
    }
    float inv = 1.f / (den + EPS_DEN);
    float4 bb = *(const float4*)(b2 + base);
    float4 o = make_float4(acc.x * inv + bb.x, acc.y * inv + bb.y,
                           acc.z * inv + bb.z, acc.w * inv + bb.w);
    *(float4*)(out + (size_t)node * C2 + base) = o;
}

// ---------------- launch ----------------
extern "C" void kernel_launch(void* const* d_in, const int* in_sizes, int n_in,
                              void* d_out, int out_size) {
    const float* x    = (const float*)d_in[0];
    const int*   ei   = (const int*)d_in[1];
    const float* Wl1  = (const float*)d_in[2];
    const float* Wr1  = (const float*)d_in[3];
    const float* att1 = (const float*)d_in[4];
    const float* b1   = (const float*)d_in[5];
    const float* Wl2  = (const float*)d_in[6];
    const float* Wr2  = (const float*)d_in[7];
    const float* att2 = (const float*)d_in[8];
    const float* b2   = (const float*)d_in[9];
    float* out = (float*)d_out;

    float *xl1, *xr1, *h, *hl2, *hr2;
    cudaGetSymbolAddress((void**)&xl1, g_xl1);
    cudaGetSymbolAddress((void**)&xr1, g_xr1);
    cudaGetSymbolAddress((void**)&h,   g_h);
    cudaGetSymbolAddress((void**)&hl2, g_hl2);
    cudaGetSymbolAddress((void**)&hr2, g_hr2);

    const int T = 256;
    // CSR build (shared by both layers)
    k_zero<<<(NNODES + T - 1) / T, T>>>();
    k_count<<<(NEDGES + T - 1) / T, T>>>(ei);
    k_scan<<<1, 1024>>>();
    k_fill<<<(NEDGES + T - 1) / T, T>>>(ei);

    // layer 1 projections: [N,128] @ [128,256]
    {
        dim3 grid((NNODES + 127) / 128, C1 / 128);
        sgemm128<<<grid, 256>>>(x, Wl1, xl1, NNODES, C1, 128);
        sgemm128<<<grid, 256>>>(x, Wr1, xr1, NNODES, C1, 128);
    }
    int nblk = (NNODES + 7) / 8;
    aggr1<<<nblk, 256>>>(att1, b1);

    // layer 2 projections: [N,256] @ [256,128]
    {
        dim3 grid((NNODES + 127) / 128, C2 / 128);
        sgemm128<<<grid, 256>>>(h, Wl2, hl2, NNODES, C2, 256);
        sgemm128<<<grid, 256>>>(h, Wr2, hr2, NNODES, C2, 256);
    }
    aggr2<<<nblk, 256>>>(att2, b2, out);
}

// round 6
// speedup vs baseline: 2.3905x; 1.6293x over previous
#include <cuda_runtime.h>
#include <cuda_bf16.h>
#include <cstdint>

#define NNODES 50000
#define NEDGES 800000
#define MPAD   50048      // 391 * 128
#define C1 256            // heads*hid layer1
#define C2 128            // out channels layer2
#define NEG_SLOPE 0.2f
#define EPS_DEN 1e-16f

// ---------------- scratch (device globals; no allocations allowed) ----------------
__device__ float g_xl1[NNODES * C1];
__device__ float g_xr1[NNODES * C1];
__device__ float g_h  [NNODES * C1];
__device__ float g_hl2[NNODES * C2];
__device__ float g_hr2[NNODES * C2];
__device__ int   g_row[NNODES + 1];
__device__ int   g_cnt[NNODES];
__device__ int   g_srcs[NEDGES];
// bf16 split buffers
__device__ __align__(16) __nv_bfloat16 g_ah[MPAD * 256];
__device__ __align__(16) __nv_bfloat16 g_al[MPAD * 256];
__device__ __align__(16) __nv_bfloat16 g_bhL[32768];
__device__ __align__(16) __nv_bfloat16 g_blL[32768];
__device__ __align__(16) __nv_bfloat16 g_bhR[32768];
__device__ __align__(16) __nv_bfloat16 g_blR[32768];

// ---------------- helpers ----------------
__device__ __forceinline__ float lrelu(float x) { return x > 0.f ? x : NEG_SLOPE * x; }

__device__ __forceinline__ uint32_t smem_u32(const void* p) {
    uint32_t a;
    asm("{ .reg .u64 t; cvta.to.shared.u64 t, %1; cvt.u32.u64 %0, t; }" : "=r"(a) : "l"(p));
    return a;
}

__device__ __forceinline__ void ldsm_x4(uint32_t* r, uint32_t addr) {
    asm volatile("ldmatrix.sync.aligned.m8n8.x4.shared.b16 {%0,%1,%2,%3}, [%4];"
                 : "=r"(r[0]), "=r"(r[1]), "=r"(r[2]), "=r"(r[3]) : "r"(addr));
}

__device__ __forceinline__ void mma_bf16(float* c, const uint32_t* a,
                                         uint32_t b0, uint32_t b1) {
    asm volatile(
        "mma.sync.aligned.m16n8k16.row.col.f32.bf16.bf16.f32 "
        "{%0,%1,%2,%3}, {%4,%5,%6,%7}, {%8,%9}, {%0,%1,%2,%3};"
        : "+f"(c[0]), "+f"(c[1]), "+f"(c[2]), "+f"(c[3])
        : "r"(a[0]), "r"(a[1]), "r"(a[2]), "r"(a[3]), "r"(b0), "r"(b1));
}

// ---------------- CSR build ----------------
__global__ void k_zero() {
    int i = blockIdx.x * blockDim.x + threadIdx.x;
    if (i < NNODES) g_cnt[i] = 0;
}
__global__ void k_count(const int* __restrict__ ei) {
    int e = blockIdx.x * blockDim.x + threadIdx.x;
    if (e < NEDGES) atomicAdd(&g_cnt[ei[NEDGES + e]], 1);
}
__global__ __launch_bounds__(1024) void k_scan() {
    __shared__ int s[1024];
    __shared__ int carry_s;
    int t = threadIdx.x;
    if (t == 0) carry_s = 0;
    __syncthreads();
    for (int base = 0; base < NNODES; base += 4096) {
        int idx = base + t * 4;
        int v0 = (idx + 0 < NNODES) ? g_cnt[idx + 0] : 0;
        int v1 = (idx + 1 < NNODES) ? g_cnt[idx + 1] : 0;
        int v2 = (idx + 2 < NNODES) ? g_cnt[idx + 2] : 0;
        int v3 = (idx + 3 < NNODES) ? g_cnt[idx + 3] : 0;
        int tot = v0 + v1 + v2 + v3;
        s[t] = tot;
        __syncthreads();
        for (int off = 1; off < 1024; off <<= 1) {
            int x = (t >= off) ? s[t - off] : 0;
            __syncthreads();
            s[t] += x;
            __syncthreads();
        }
        int excl = carry_s + s[t] - tot;
        if (idx + 0 < NNODES) { g_row[idx + 0] = excl;                g_cnt[idx + 0] = 0; }
        if (idx + 1 < NNODES) { g_row[idx + 1] = excl + v0;           g_cnt[idx + 1] = 0; }
        if (idx + 2 < NNODES) { g_row[idx + 2] = excl + v0 + v1;      g_cnt[idx + 2] = 0; }
        if (idx + 3 < NNODES) { g_row[idx + 3] = excl + v0 + v1 + v2; g_cnt[idx + 3] = 0; }
        __syncthreads();
        if (t == 1023) carry_s += s[1023];
        __syncthreads();
    }
    if (t == 0) g_row[NNODES] = NEDGES;
}
__global__ void k_fill(const int* __restrict__ ei) {
    int e = blockIdx.x * blockDim.x + threadIdx.x;
    if (e >= NEDGES) return;
    int dst = ei[NEDGES + e];
    int pos = g_row[dst] + atomicAdd(&g_cnt[dst], 1);
    g_srcs[pos] = ei[e];
}

// ---------------- bf16 hi/lo splits ----------------
__global__ void k_split(const float* __restrict__ A, int M, int K) {
    int i = blockIdx.x * blockDim.x + threadIdx.x;
    if (i >= MPAD * K) return;
    int m = i / K;
    float v = (m < M) ? A[i] : 0.f;
    __nv_bfloat16 h = __float2bfloat16(v);
    g_ah[i] = h;
    g_al[i] = __float2bfloat16(v - __bfloat162float(h));
}
// W [K x Nn] fp32 -> bh/bl [Nn x K] bf16 (transposed)
__global__ void k_splitw(const float* __restrict__ W, __nv_bfloat16* __restrict__ bh,
                         __nv_bfloat16* __restrict__ bl, int K, int Nn) {
    int i = blockIdx.x * blockDim.x + threadIdx.x;
    if (i >= K * Nn) return;
    int k = i / Nn, n = i - k * Nn;
    float v = W[i];
    __nv_bfloat16 h = __float2bfloat16(v);
    bh[n * K + k] = h;
    bl[n * K + k] = __float2bfloat16(v - __bfloat162float(h));
}

// ---------------- warp-MMA bf16x3 GEMM --------------------------------------------
// Cd[M,NPER] = A[M,KT] @ W for two weight matrices (mat picked by blockIdx.y).
// 3-term split: Ah*Bh + Ah*Bl + Al*Bh. CTA tile 128x128, 8 warps (4x2), warp 32x64.
template <int KT, int NPER>
__global__ __launch_bounds__(256) void mgemm(
    const __nv_bfloat16* __restrict__ Ah, const __nv_bfloat16* __restrict__ Al,
    const __nv_bfloat16* __restrict__ Bh0, const __nv_bfloat16* __restrict__ Bl0,
    const __nv_bfloat16* __restrict__ Bh1, const __nv_bfloat16* __restrict__ Bl1,
    float* __restrict__ Cd0, float* __restrict__ Cd1) {
    constexpr int KCH = KT / 64;       // 64-wide k-chunks per term
    constexpr int NB  = NPER / 128;    // CTA n-tiles per matrix
    __shared__ __nv_bfloat16 As[128][72];   // 64 data + 8 pad (144B rows)
    __shared__ __nv_bfloat16 Bs[128][72];

    const int tid = threadIdx.x, wid = tid >> 5, lane = tid & 31;
    const int mat  = blockIdx.y / NB;
    const int ncol = (blockIdx.y % NB) * 128;
    const __nv_bfloat16* Bh = mat ? Bh1 : Bh0;
    const __nv_bfloat16* Bl = mat ? Bl1 : Bl0;
    float* Cd = mat ? Cd1 : Cd0;
    const size_t blockM = (size_t)blockIdx.x * 128;

    const int wm = wid >> 1, wn = wid & 1;     // 4x2 warp grid
    float acc[2][8][4];
#pragma unroll
    for (int mi = 0; mi < 2; mi++)
#pragma unroll
        for (int ni = 0; ni < 8; ni++)
#pragma unroll
            for (int q = 0; q < 4; q++) acc[mi][ni][q] = 0.f;

    // ldmatrix per-lane offsets
    const int a_r = (lane & 7) + ((lane >> 3) & 1) * 8;
    const int a_c = (lane >> 4) * 8;
    const int b_r = (lane & 7) + (lane >> 4) * 8;
    const int b_c = ((lane >> 3) & 1) * 8;

    for (int c = 0; c < 3 * KCH; c++) {
        int seg = c / KCH;
        int kc = (c - seg * KCH) * 64;
        const __nv_bfloat16* Asrc = (seg == 2) ? Al : Ah;
        const __nv_bfloat16* Bsrc = (seg == 1) ? Bl : Bh;
#pragma unroll
        for (int u = tid; u < 1024; u += 256) {
            int r = u >> 3, j = u & 7;
            *(uint4*)((char*)&As[r][0] + j * 16) =
                *(const uint4*)(Asrc + (blockM + r) * KT + kc + j * 8);
            *(uint4*)((char*)&Bs[r][0] + j * 16) =
                *(const uint4*)(Bsrc + (size_t)(ncol + r) * KT + kc + j * 8);
        }
        __syncthreads();
#pragma unroll
        for (int ks = 0; ks < 4; ks++) {
            int k0 = ks * 16;
            uint32_t a[2][4];
#pragma unroll
            for (int mi = 0; mi < 2; mi++)
                ldsm_x4(a[mi], smem_u32(&As[wm * 32 + mi * 16 + a_r][k0 + a_c]));
            uint32_t b[4][4];
#pragma unroll
            for (int np = 0; np < 4; np++)
                ldsm_x4(b[np], smem_u32(&Bs[wn * 64 + np * 16 + b_r][k0 + b_c]));
#pragma unroll
            for (int mi = 0; mi < 2; mi++)
#pragma unroll
                for (int ni = 0; ni < 8; ni++)
                    mma_bf16(acc[mi][ni], a[mi],
                             b[ni >> 1][(ni & 1) * 2], b[ni >> 1][(ni & 1) * 2 + 1]);
        }
        __syncthreads();
    }

    // epilogue: fp32 store, guard M
#pragma unroll
    for (int mi = 0; mi < 2; mi++) {
        int r0 = (int)blockM + wm * 32 + mi * 16 + (lane >> 2);
#pragma unroll
        for (int ni = 0; ni < 8; ni++) {
            int col = ncol + wn * 64 + ni * 8 + (lane & 3) * 2;
            if (r0 < NNODES)
                *(float2*)&Cd[(size_t)r0 * NPER + col] =
                    make_float2(acc[mi][ni][0], acc[mi][ni][1]);
            if (r0 + 8 < NNODES)
                *(float2*)&Cd[(size_t)(r0 + 8) * NPER + col] =
                    make_float2(acc[mi][ni][2], acc[mi][ni][3]);
        }
    }
}

// ---------------- layer 1 aggregation: one warp per dst node ----------------
__global__ __launch_bounds__(256) void aggr1(const float* __restrict__ att,
                                             const float* __restrict__ b1) {
    int node = blockIdx.x * 8 + (threadIdx.x >> 5);
    if (node >= NNODES) return;
    int lane = threadIdx.x & 31;
    int beg = g_row[node], end = g_row[node + 1];
    int base = lane * 8;

    const float4* pr = (const float4*)(g_xr1 + (size_t)node * C1 + base);
    float4 r0 = pr[0], r1 = pr[1];
    const float4* pa = (const float4*)(att + base);
    float4 t0 = pa[0], t1 = pa[1];

    float acc[8];
#pragma unroll
    for (int j = 0; j < 8; j++) acc[j] = 0.f;
    float den = 0.f;

    for (int i = beg; i < end; i++) {
        int src = g_srcs[i];
        const float4* pl = (const float4*)(g_xl1 + (size_t)src * C1 + base);
        float4 a0 = pl[0], a1 = pl[1];
        float s = lrelu(a0.x + r0.x) * t0.x + lrelu(a0.y + r0.y) * t0.y +
                  lrelu(a0.z + r0.z) * t0.z + lrelu(a0.w + r0.w) * t0.w +
                  lrelu(a1.x + r1.x) * t1.x + lrelu(a1.y + r1.y) * t1.y +
                  lrelu(a1.z + r1.z) * t1.z + lrelu(a1.w + r1.w) * t1.w;
        s += __shfl_xor_sync(0xffffffffu, s, 1);
        s += __shfl_xor_sync(0xffffffffu, s, 2);
        s += __shfl_xor_sync(0xffffffffu, s, 4);
        float ee = __expf(s);
        acc[0] = fmaf(ee, a0.x, acc[0]);
        acc[1] = fmaf(ee, a0.y, acc[1]);
        acc[2] = fmaf(ee, a0.z, acc[2]);
        acc[3] = fmaf(ee, a0.w, acc[3]);
        acc[4] = fmaf(ee, a1.x, acc[4]);
        acc[5] = fmaf(ee, a1.y, acc[5]);
        acc[6] = fmaf(ee, a1.z, acc[6]);
        acc[7] = fmaf(ee, a1.w, acc[7]);
        den += ee;
    }
    float inv = 1.f / (den + EPS_DEN);
    const float4* pb = (const float4*)(b1 + base);
    float4 bb0 = pb[0], bb1 = pb[1];
    float o[8];
    o[0] = acc[0] * inv + bb0.x;  o[1] = acc[1] * inv + bb0.y;
    o[2] = acc[2] * inv + bb0.z;  o[3] = acc[3] * inv + bb0.w;
    o[4] = acc[4] * inv + bb1.x;  o[5] = acc[5] * inv + bb1.y;
    o[6] = acc[6] * inv + bb1.z;  o[7] = acc[7] * inv + bb1.w;
#pragma unroll
    for (int j = 0; j < 8; j++) o[j] = o[j] > 0.f ? o[j] : expm1f(o[j]);
    float4* po = (float4*)(g_h + (size_t)node * C1 + base);
    po[0] = make_float4(o[0], o[1], o[2], o[3]);
    po[1] = make_float4(o[4], o[5], o[6], o[7]);
}

// ---------------- layer 2 aggregation ----------------
__global__ __launch_bounds__(256) void aggr2(const float* __restrict__ att,
                                             const float* __restrict__ b2,
                                             float* __restrict__ out) {
    int node = blockIdx.x * 8 + (threadIdx.x >> 5);
    if (node >= NNODES) return;
    int lane = threadIdx.x & 31;
    int beg = g_row[node], end = g_row[node + 1];
    int base = lane * 4;

    float4 r = *(const float4*)(g_hr2 + (size_t)node * C2 + base);
    float4 t = *(const float4*)(att + base);

    float4 acc = make_float4(0.f, 0.f, 0.f, 0.f);
    float den = 0.f;

    for (int i = beg; i < end; i++) {
        int src = g_srcs[i];
        float4 a = *(const float4*)(g_hl2 + (size_t)src * C2 + base);
        float s = lrelu(a.x + r.x) * t.x + lrelu(a.y + r.y) * t.y +
                  lrelu(a.z + r.z) * t.z + lrelu(a.w + r.w) * t.w;
#pragma unroll
        for (int d = 16; d >= 1; d >>= 1) s += __shfl_xor_sync(0xffffffffu, s, d);
        float ee = __expf(s);
        acc.x = fmaf(ee, a.x, acc.x);
        acc.y = fmaf(ee, a.y, acc.y);
        acc.z = fmaf(ee, a.z, acc.z);
        acc.w = fmaf(ee, a.w, acc.w);
        den += ee;
    }
    float inv = 1.f / (den + EPS_DEN);
    float4 bb = *(const float4*)(b2 + base);
    *(float4*)(out + (size_t)node * C2 + base) =
        make_float4(acc.x * inv + bb.x, acc.y * inv + bb.y,
                    acc.z * inv + bb.z, acc.w * inv + bb.w);
}

// ---------------- launch ----------------
extern "C" void kernel_launch(void* const* d_in, const int* in_sizes, int n_in,
                              void* d_out, int out_size) {
    const float* x    = (const float*)d_in[0];
    const int*   ei   = (const int*)d_in[1];
    const float* Wl1  = (const float*)d_in[2];
    const float* Wr1  = (const float*)d_in[3];
    const float* att1 = (const float*)d_in[4];
    const float* b1   = (const float*)d_in[5];
    const float* Wl2  = (const float*)d_in[6];
    const float* Wr2  = (const float*)d_in[7];
    const float* att2 = (const float*)d_in[8];
    const float* b2   = (const float*)d_in[9];
    float* out = (float*)d_out;

    float *xl1, *xr1, *h, *hl2, *hr2;
    __nv_bfloat16 *ah, *al, *bhL, *blL, *bhR, *blR;
    cudaGetSymbolAddress((void**)&xl1, g_xl1);
    cudaGetSymbolAddress((void**)&xr1, g_xr1);
    cudaGetSymbolAddress((void**)&h,   g_h);
    cudaGetSymbolAddress((void**)&hl2, g_hl2);
    cudaGetSymbolAddress((void**)&hr2, g_hr2);
    cudaGetSymbolAddress((void**)&ah,  g_ah);
    cudaGetSymbolAddress((void**)&al,  g_al);
    cudaGetSymbolAddress((void**)&bhL, g_bhL);
    cudaGetSymbolAddress((void**)&blL, g_blL);
    cudaGetSymbolAddress((void**)&bhR, g_bhR);
    cudaGetSymbolAddress((void**)&blR, g_blR);

    const int T = 256;
    // CSR build (shared by both layers)
    k_zero<<<(NNODES + T - 1) / T, T>>>();
    k_count<<<(NEDGES + T - 1) / T, T>>>(ei);
    k_scan<<<1, 1024>>>();
    k_fill<<<(NEDGES + T - 1) / T, T>>>(ei);

    // layer 1: split + fused dual GEMM [MPAD,128] @ [128,256] x2
    k_splitw<<<(128 * 256 + T - 1) / T, T>>>(Wl1, bhL, blL, 128, 256);
    k_splitw<<<(128 * 256 + T - 1) / T, T>>>(Wr1, bhR, blR, 128, 256);
    k_split<<<(MPAD * 128 + T - 1) / T, T>>>(x, NNODES, 128);
    {
        dim3 grid(MPAD / 128, 4);
        mgemm<128, 256><<<grid, 256>>>(ah, al, bhL, blL, bhR, blR, xl1, xr1);
    }
    int nblk = (NNODES + 7) / 8;
    aggr1<<<nblk, 256>>>(att1, b1);

    // layer 2: split + fused dual GEMM [MPAD,256] @ [256,128] x2
    k_splitw<<<(256 * 128 + T - 1) / T, T>>>(Wl2, bhL, blL, 256, 128);
    k_splitw<<<(256 * 128 + T - 1) / T, T>>>(Wr2, bhR, blR, 256, 128);
    k_split<<<(MPAD * 256 + T - 1) / T, T>>>(h, NNODES, 256);
    {
        dim3 grid(MPAD / 128, 2);
        mgemm<256, 128><<<grid, 256>>>(ah, al, bhL, blL, bhR, blR, hl2, hr2);
    }
    aggr2<<<nblk, 256>>>(att2, b2, out);
}

// round 7
// speedup vs baseline: 2.4126x; 1.0093x over previous
#include <cuda_runtime.h>
#include <cuda_bf16.h>
#include <cstdint>

#define NNODES 50000
#define NEDGES 800000
#define MPAD   50048      // 391 * 128
#define C1 256            // heads*hid layer1
#define C2 128            // out channels layer2
#define NEG_SLOPE 0.2f
#define EPS_DEN 1e-16f

// ---------------- scratch (device globals; no allocations allowed) ----------------
__device__ float g_xl1[NNODES * C1];
__device__ float g_xr1[NNODES * C1];
__device__ float g_h  [NNODES * C1];
__device__ float g_hl2[NNODES * C2];
__device__ float g_hr2[NNODES * C2];
__device__ int   g_row[NNODES + 1];
__device__ int   g_cnt[NNODES];
__device__ int   g_srcs[NEDGES];
// bf16 split buffers
__device__ __align__(16) __nv_bfloat16 g_ah[MPAD * 256];
__device__ __align__(16) __nv_bfloat16 g_al[MPAD * 256];
__device__ __align__(16) __nv_bfloat16 g_bhL[32768];
__device__ __align__(16) __nv_bfloat16 g_blL[32768];
__device__ __align__(16) __nv_bfloat16 g_bhR[32768];
__device__ __align__(16) __nv_bfloat16 g_blR[32768];

// ---------------- helpers ----------------
__device__ __forceinline__ float lrelu(float x) { return x > 0.f ? x : NEG_SLOPE * x; }

__device__ __forceinline__ uint32_t smem_u32(const void* p) {
    uint32_t a;
    asm("{ .reg .u64 t; cvta.to.shared.u64 t, %1; cvt.u32.u64 %0, t; }" : "=r"(a) : "l"(p));
    return a;
}

__device__ __forceinline__ void ldsm_x4(uint32_t* r, uint32_t addr) {
    asm volatile("ldmatrix.sync.aligned.m8n8.x4.shared.b16 {%0,%1,%2,%3}, [%4];"
                 : "=r"(r[0]), "=r"(r[1]), "=r"(r[2]), "=r"(r[3]) : "r"(addr));
}

__device__ __forceinline__ void mma_bf16(float* c, const uint32_t* a,
                                         uint32_t b0, uint32_t b1) {
    asm volatile(
        "mma.sync.aligned.m16n8k16.row.col.f32.bf16.bf16.f32 "
        "{%0,%1,%2,%3}, {%4,%5,%6,%7}, {%8,%9}, {%0,%1,%2,%3};"
        : "+f"(c[0]), "+f"(c[1]), "+f"(c[2]), "+f"(c[3])
        : "r"(a[0]), "r"(a[1]), "r"(a[2]), "r"(a[3]), "r"(b0), "r"(b1));
}

// ---------------- CSR build ----------------
__global__ void k_zero() {
    int i = blockIdx.x * blockDim.x + threadIdx.x;
    if (i < NNODES) g_cnt[i] = 0;
}
__global__ void k_count(const int* __restrict__ ei) {
    int e = blockIdx.x * blockDim.x + threadIdx.x;
    if (e < NEDGES) atomicAdd(&g_cnt[ei[NEDGES + e]], 1);
}
__global__ __launch_bounds__(1024) void k_scan() {
    __shared__ int s[1024];
    __shared__ int carry_s;
    int t = threadIdx.x;
    if (t == 0) carry_s = 0;
    __syncthreads();
    for (int base = 0; base < NNODES; base += 4096) {
        int idx = base + t * 4;
        int v0 = (idx + 0 < NNODES) ? g_cnt[idx + 0] : 0;
        int v1 = (idx + 1 < NNODES) ? g_cnt[idx + 1] : 0;
        int v2 = (idx + 2 < NNODES) ? g_cnt[idx + 2] : 0;
        int v3 = (idx + 3 < NNODES) ? g_cnt[idx + 3] : 0;
        int tot = v0 + v1 + v2 + v3;
        s[t] = tot;
        __syncthreads();
        for (int off = 1; off < 1024; off <<= 1) {
            int x = (t >= off) ? s[t - off] : 0;
            __syncthreads();
            s[t] += x;
            __syncthreads();
        }
        int excl = carry_s + s[t] - tot;
        if (idx + 0 < NNODES) { g_row[idx + 0] = excl;                g_cnt[idx + 0] = 0; }
        if (idx + 1 < NNODES) { g_row[idx + 1] = excl + v0;           g_cnt[idx + 1] = 0; }
        if (idx + 2 < NNODES) { g_row[idx + 2] = excl + v0 + v1;      g_cnt[idx + 2] = 0; }
        if (idx + 3 < NNODES) { g_row[idx + 3] = excl + v0 + v1 + v2; g_cnt[idx + 3] = 0; }
        __syncthreads();
        if (t == 1023) carry_s += s[1023];
        __syncthreads();
    }
    if (t == 0) g_row[NNODES] = NEDGES;
}
__global__ void k_fill(const int* __restrict__ ei) {
    int e = blockIdx.x * blockDim.x + threadIdx.x;
    if (e >= NEDGES) return;
    int dst = ei[NEDGES + e];
    int pos = g_row[dst] + atomicAdd(&g_cnt[dst], 1);
    g_srcs[pos] = ei[e];
}

// ---------------- bf16 hi/lo splits ----------------
__global__ void k_split(const float* __restrict__ A, int M, int K) {
    int i = blockIdx.x * blockDim.x + threadIdx.x;
    if (i >= MPAD * K) return;
    int m = i / K;
    float v = (m < M) ? A[i] : 0.f;
    __nv_bfloat16 h = __float2bfloat16(v);
    g_ah[i] = h;
    g_al[i] = __float2bfloat16(v - __bfloat162float(h));
}
// W [K x Nn] fp32 -> bh/bl [Nn x K] bf16 (transposed)
__global__ void k_splitw(const float* __restrict__ W, __nv_bfloat16* __restrict__ bh,
                         __nv_bfloat16* __restrict__ bl, int K, int Nn) {
    int i = blockIdx.x * blockDim.x + threadIdx.x;
    if (i >= K * Nn) return;
    int k = i / Nn, n = i - k * Nn;
    float v = W[i];
    __nv_bfloat16 h = __float2bfloat16(v);
    bh[n * K + k] = h;
    bl[n * K + k] = __float2bfloat16(v - __bfloat162float(h));
}

// ---------------- warp-MMA bf16x3 GEMM --------------------------------------------
template <int KT, int NPER>
__global__ __launch_bounds__(256) void mgemm(
    const __nv_bfloat16* __restrict__ Ah, const __nv_bfloat16* __restrict__ Al,
    const __nv_bfloat16* __restrict__ Bh0, const __nv_bfloat16* __restrict__ Bl0,
    const __nv_bfloat16* __restrict__ Bh1, const __nv_bfloat16* __restrict__ Bl1,
    float* __restrict__ Cd0, float* __restrict__ Cd1) {
    constexpr int KCH = KT / 64;
    constexpr int NB  = NPER / 128;
    __shared__ __nv_bfloat16 As[128][72];
    __shared__ __nv_bfloat16 Bs[128][72];

    const int tid = threadIdx.x, wid = tid >> 5, lane = tid & 31;
    const int mat  = blockIdx.y / NB;
    const int ncol = (blockIdx.y % NB) * 128;
    const __nv_bfloat16* Bh = mat ? Bh1 : Bh0;
    const __nv_bfloat16* Bl = mat ? Bl1 : Bl0;
    float* Cd = mat ? Cd1 : Cd0;
    const size_t blockM = (size_t)blockIdx.x * 128;

    const int wm = wid >> 1, wn = wid & 1;
    float acc[2][8][4];
#pragma unroll
    for (int mi = 0; mi < 2; mi++)
#pragma unroll
        for (int ni = 0; ni < 8; ni++)
#pragma unroll
            for (int q = 0; q < 4; q++) acc[mi][ni][q] = 0.f;

    const int a_r = (lane & 7) + ((lane >> 3) & 1) * 8;
    const int a_c = (lane >> 4) * 8;
    const int b_r = (lane & 7) + (lane >> 4) * 8;
    const int b_c = ((lane >> 3) & 1) * 8;

    for (int c = 0; c < 3 * KCH; c++) {
        int seg = c / KCH;
        int kc = (c - seg * KCH) * 64;
        const __nv_bfloat16* Asrc = (seg == 2) ? Al : Ah;
        const __nv_bfloat16* Bsrc = (seg == 1) ? Bl : Bh;
#pragma unroll
        for (int u = tid; u < 1024; u += 256) {
            int r = u >> 3, j = u & 7;
            *(uint4*)((char*)&As[r][0] + j * 16) =
                *(const uint4*)(Asrc + (blockM + r) * KT + kc + j * 8);
            *(uint4*)((char*)&Bs[r][0] + j * 16) =
                *(const uint4*)(Bsrc + (size_t)(ncol + r) * KT + kc + j * 8);
        }
        __syncthreads();
#pragma unroll
        for (int ks = 0; ks < 4; ks++) {
            int k0 = ks * 16;
            uint32_t a[2][4];
#pragma unroll
            for (int mi = 0; mi < 2; mi++)
                ldsm_x4(a[mi], smem_u32(&As[wm * 32 + mi * 16 + a_r][k0 + a_c]));
            uint32_t b[4][4];
#pragma unroll
            for (int np = 0; np < 4; np++)
                ldsm_x4(b[np], smem_u32(&Bs[wn * 64 + np * 16 + b_r][k0 + b_c]));
#pragma unroll
            for (int mi = 0; mi < 2; mi++)
#pragma unroll
                for (int ni = 0; ni < 8; ni++)
                    mma_bf16(acc[mi][ni], a[mi],
                             b[ni >> 1][(ni & 1) * 2], b[ni >> 1][(ni & 1) * 2 + 1]);
        }
        __syncthreads();
    }

#pragma unroll
    for (int mi = 0; mi < 2; mi++) {
        int r0 = (int)blockM + wm * 32 + mi * 16 + (lane >> 2);
#pragma unroll
        for (int ni = 0; ni < 8; ni++) {
            int col = ncol + wn * 64 + ni * 8 + (lane & 3) * 2;
            if (r0 < NNODES)
                *(float2*)&Cd[(size_t)r0 * NPER + col] =
                    make_float2(acc[mi][ni][0], acc[mi][ni][1]);
            if (r0 + 8 < NNODES)
                *(float2*)&Cd[(size_t)(r0 + 8) * NPER + col] =
                    make_float2(acc[mi][ni][2], acc[mi][ni][3]);
        }
    }
}

// ---------------- layer 1 aggregation: one warp per dst node, 2-edge pipeline -----
__global__ __launch_bounds__(256) void aggr1(const float* __restrict__ att,
                                             const float* __restrict__ b1) {
    int node = blockIdx.x * 8 + (threadIdx.x >> 5);
    if (node >= NNODES) return;
    int lane = threadIdx.x & 31;
    int beg = g_row[node], end = g_row[node + 1];
    int base = lane * 8;

    const float4* pr = (const float4*)(g_xr1 + (size_t)node * C1 + base);
    float4 r0 = pr[0], r1 = pr[1];
    const float4* pa = (const float4*)(att + base);
    float4 t0 = pa[0], t1 = pa[1];

    float acc[8];
#pragma unroll
    for (int j = 0; j < 8; j++) acc[j] = 0.f;
    float den = 0.f;

    int i = beg;
    while (i < end) {
        int cnt = min(32, end - i);
        int mysrc = __ldg(&g_srcs[min(i + lane, end - 1)]);
        int j = 0;
        for (; j + 2 <= cnt; j += 2) {
            int s0 = __shfl_sync(0xffffffffu, mysrc, j);
            int s1 = __shfl_sync(0xffffffffu, mysrc, j + 1);
            const float4* p0 = (const float4*)(g_xl1 + (size_t)s0 * C1 + base);
            const float4* p1 = (const float4*)(g_xl1 + (size_t)s1 * C1 + base);
            float4 a0 = __ldg(p0), a1 = __ldg(p0 + 1);
            float4 c0 = __ldg(p1), c1 = __ldg(p1 + 1);
            float sA = lrelu(a0.x + r0.x) * t0.x + lrelu(a0.y + r0.y) * t0.y +
                       lrelu(a0.z + r0.z) * t0.z + lrelu(a0.w + r0.w) * t0.w +
                       lrelu(a1.x + r1.x) * t1.x + lrelu(a1.y + r1.y) * t1.y +
                       lrelu(a1.z + r1.z) * t1.z + lrelu(a1.w + r1.w) * t1.w;
            float sB = lrelu(c0.x + r0.x) * t0.x + lrelu(c0.y + r0.y) * t0.y +
                       lrelu(c0.z + r0.z) * t0.z + lrelu(c0.w + r0.w) * t0.w +
                       lrelu(c1.x + r1.x) * t1.x + lrelu(c1.y + r1.y) * t1.y +
                       lrelu(c1.z + r1.z) * t1.z + lrelu(c1.w + r1.w) * t1.w;
            // interleaved shuffle reductions (overlap latencies)
            sA += __shfl_xor_sync(0xffffffffu, sA, 1);
            sB += __shfl_xor_sync(0xffffffffu, sB, 1);
            sA += __shfl_xor_sync(0xffffffffu, sA, 2);
            sB += __shfl_xor_sync(0xffffffffu, sB, 2);
            sA += __shfl_xor_sync(0xffffffffu, sA, 4);
            sB += __shfl_xor_sync(0xffffffffu, sB, 4);
            float eA = __expf(sA);
            float eB = __expf(sB);
            acc[0] = fmaf(eA, a0.x, acc[0]); acc[0] = fmaf(eB, c0.x, acc[0]);
            acc[1] = fmaf(eA, a0.y, acc[1]); acc[1] = fmaf(eB, c0.y, acc[1]);
            acc[2] = fmaf(eA, a0.z, acc[2]); acc[2] = fmaf(eB, c0.z, acc[2]);
            acc[3] = fmaf(eA, a0.w, acc[3]); acc[3] = fmaf(eB, c0.w, acc[3]);
            acc[4] = fmaf(eA, a1.x, acc[4]); acc[4] = fmaf(eB, c1.x, acc[4]);
            acc[5] = fmaf(eA, a1.y, acc[5]); acc[5] = fmaf(eB, c1.y, acc[5]);
            acc[6] = fmaf(eA, a1.z, acc[6]); acc[6] = fmaf(eB, c1.z, acc[6]);
            acc[7] = fmaf(eA, a1.w, acc[7]); acc[7] = fmaf(eB, c1.w, acc[7]);
            den += eA + eB;
        }
        if (j < cnt) {
            int s0 = __shfl_sync(0xffffffffu, mysrc, j);
            const float4* p0 = (const float4*)(g_xl1 + (size_t)s0 * C1 + base);
            float4 a0 = __ldg(p0), a1 = __ldg(p0 + 1);
            float sA = lrelu(a0.x + r0.x) * t0.x + lrelu(a0.y + r0.y) * t0.y +
                       lrelu(a0.z + r0.z) * t0.z + lrelu(a0.w + r0.w) * t0.w +
                       lrelu(a1.x + r1.x) * t1.x + lrelu(a1.y + r1.y) * t1.y +
                       lrelu(a1.z + r1.z) * t1.z + lrelu(a1.w + r1.w) * t1.w;
            sA += __shfl_xor_sync(0xffffffffu, sA, 1);
            sA += __shfl_xor_sync(0xffffffffu, sA, 2);
            sA += __shfl_xor_sync(0xffffffffu, sA, 4);
            float eA = __expf(sA);
            acc[0] = fmaf(eA, a0.x, acc[0]);
            acc[1] = fmaf(eA, a0.y, acc[1]);
            acc[2] = fmaf(eA, a0.z, acc[2]);
            acc[3] = fmaf(eA, a0.w, acc[3]);
            acc[4] = fmaf(eA, a1.x, acc[4]);
            acc[5] = fmaf(eA, a1.y, acc[5]);
            acc[6] = fmaf(eA, a1.z, acc[6]);
            acc[7] = fmaf(eA, a1.w, acc[7]);
            den += eA;
        }
        i += cnt;
    }
    float inv = 1.f / (den + EPS_DEN);
    const float4* pb = (const float4*)(b1 + base);
    float4 bb0 = pb[0], bb1 = pb[1];
    float o[8];
    o[0] = acc[0] * inv + bb0.x;  o[1] = acc[1] * inv + bb0.y;
    o[2] = acc[2] * inv + bb0.z;  o[3] = acc[3] * inv + bb0.w;
    o[4] = acc[4] * inv + bb1.x;  o[5] = acc[5] * inv + bb1.y;
    o[6] = acc[6] * inv + bb1.z;  o[7] = acc[7] * inv + bb1.w;
#pragma unroll
    for (int j = 0; j < 8; j++) o[j] = o[j] > 0.f ? o[j] : expm1f(o[j]);
    float4* po = (float4*)(g_h + (size_t)node * C1 + base);
    po[0] = make_float4(o[0], o[1], o[2], o[3]);
    po[1] = make_float4(o[4], o[5], o[6], o[7]);
}

// ---------------- layer 2 aggregation: 2-edge pipeline ----------------
__global__ __launch_bounds__(256) void aggr2(const float* __restrict__ att,
                                             const float* __restrict__ b2,
                                             float* __restrict__ out) {
    int node = blockIdx.x * 8 + (threadIdx.x >> 5);
    if (node >= NNODES) return;
    int lane = threadIdx.x & 31;
    int beg = g_row[node], end = g_row[node + 1];
    int base = lane * 4;

    float4 r = *(const float4*)(g_hr2 + (size_t)node * C2 + base);
    float4 t = *(const float4*)(att + base);

    float4 acc = make_float4(0.f, 0.f, 0.f, 0.f);
    float den = 0.f;

    int i = beg;
    while (i < end) {
        int cnt = min(32, end - i);
        int mysrc = __ldg(&g_srcs[min(i + lane, end - 1)]);
        int j = 0;
        for (; j + 2 <= cnt; j += 2) {
            int s0 = __shfl_sync(0xffffffffu, mysrc, j);
            int s1 = __shfl_sync(0xffffffffu, mysrc, j + 1);
            float4 a = __ldg((const float4*)(g_hl2 + (size_t)s0 * C2 + base));
            float4 c = __ldg((const float4*)(g_hl2 + (size_t)s1 * C2 + base));
            float sA = lrelu(a.x + r.x) * t.x + lrelu(a.y + r.y) * t.y +
                       lrelu(a.z + r.z) * t.z + lrelu(a.w + r.w) * t.w;
            float sB = lrelu(c.x + r.x) * t.x + lrelu(c.y + r.y) * t.y +
                       lrelu(c.z + r.z) * t.z + lrelu(c.w + r.w) * t.w;
#pragma unroll
            for (int d = 16; d >= 1; d >>= 1) {
                sA += __shfl_xor_sync(0xffffffffu, sA, d);
                sB += __shfl_xor_sync(0xffffffffu, sB, d);
            }
            float eA = __expf(sA);
            float eB = __expf(sB);
            acc.x = fmaf(eA, a.x, acc.x); acc.x = fmaf(eB, c.x, acc.x);
            acc.y = fmaf(eA, a.y, acc.y); acc.y = fmaf(eB, c.y, acc.y);
            acc.z = fmaf(eA, a.z, acc.z); acc.z = fmaf(eB, c.z, acc.z);
            acc.w = fmaf(eA, a.w, acc.w); acc.w = fmaf(eB, c.w, acc.w);
            den += eA + eB;
        }
        if (j < cnt) {
            int s0 = __shfl_sync(0xffffffffu, mysrc, j);
            float4 a = __ldg((const float4*)(g_hl2 + (size_t)s0 * C2 + base));
            float sA = lrelu(a.x + r.x) * t.x + lrelu(a.y + r.y) * t.y +
                       lrelu(a.z + r.z) * t.z + lrelu(a.w + r.w) * t.w;
#pragma unroll
            for (int d = 16; d >= 1; d >>= 1)
                sA += __shfl_xor_sync(0xffffffffu, sA, d);
            float eA = __expf(sA);
            acc.x = fmaf(eA, a.x, acc.x);
            acc.y = fmaf(eA, a.y, acc.y);
            acc.z = fmaf(eA, a.z, acc.z);
            acc.w = fmaf(eA, a.w, acc.w);
            den += eA;
        }
        i += cnt;
    }
    float inv = 1.f / (den + EPS_DEN);
    float4 bb = *(const float4*)(b2 + base);
    *(float4*)(out + (size_t)node * C2 + base) =
        make_float4(acc.x * inv + bb.x, acc.y * inv + bb.y,
                    acc.z * inv + bb.z, acc.w * inv + bb.w);
}

// ---------------- launch ----------------
extern "C" void kernel_launch(void* const* d_in, const int* in_sizes, int n_in,
                              void* d_out, int out_size) {
    const float* x    = (const float*)d_in[0];
    const int*   ei   = (const int*)d_in[1];
    const float* Wl1  = (const float*)d_in[2];
    const float* Wr1  = (const float*)d_in[3];
    const float* att1 = (const float*)d_in[4];
    const float* b1   = (const float*)d_in[5];
    const float* Wl2  = (const float*)d_in[6];
    const float* Wr2  = (const float*)d_in[7];
    const float* att2 = (const float*)d_in[8];
    const float* b2   = (const float*)d_in[9];
    float* out = (float*)d_out;

    float *xl1, *xr1, *h, *hl2, *hr2;
    __nv_bfloat16 *ah, *al, *bhL, *blL, *bhR, *blR;
    cudaGetSymbolAddress((void**)&xl1, g_xl1);
    cudaGetSymbolAddress((void**)&xr1, g_xr1);
    cudaGetSymbolAddress((void**)&h,   g_h);
    cudaGetSymbolAddress((void**)&hl2, g_hl2);
    cudaGetSymbolAddress((void**)&hr2, g_hr2);
    cudaGetSymbolAddress((void**)&ah,  g_ah);
    cudaGetSymbolAddress((void**)&al,  g_al);
    cudaGetSymbolAddress((void**)&bhL, g_bhL);
    cudaGetSymbolAddress((void**)&blL, g_blL);
    cudaGetSymbolAddress((void**)&bhR, g_bhR);
    cudaGetSymbolAddress((void**)&blR, g_blR);

    const int T = 256;
    // CSR build (shared by both layers)
    k_zero<<<(NNODES + T - 1) / T, T>>>();
    k_count<<<(NEDGES + T - 1) / T, T>>>(ei);
    k_scan<<<1, 1024>>>();
    k_fill<<<(NEDGES + T - 1) / T, T>>>(ei);

    // layer 1: split + fused dual GEMM [MPAD,128] @ [128,256] x2
    k_splitw<<<(128 * 256 + T - 1) / T, T>>>(Wl1, bhL, blL, 128, 256);
    k_splitw<<<(128 * 256 + T - 1) / T, T>>>(Wr1, bhR, blR, 128, 256);
    k_split<<<(MPAD * 128 + T - 1) / T, T>>>(x, NNODES, 128);
    {
        dim3 grid(MPAD / 128, 4);
        mgemm<128, 256><<<grid, 256>>>(ah, al, bhL, blL, bhR, blR, xl1, xr1);
    }
    int nblk = (NNODES + 7) / 8;
    aggr1<<<nblk, 256>>>(att1, b1);

    // layer 2: split + fused dual GEMM [MPAD,256] @ [256,128] x2
    k_splitw<<<(256 * 128 + T - 1) / T, T>>>(Wl2, bhL, blL, 256, 128);
    k_splitw<<<(256 * 128 + T - 1) / T, T>>>(Wr2, bhR, blR, 256, 128);
    k_split<<<(MPAD * 256 + T - 1) / T, T>>>(h, NNODES, 256);
    {
        dim3 grid(MPAD / 128, 2);
        mgemm<256, 128><<<grid, 256>>>(ah, al, bhL, blL, bhR, blR, hl2, hr2);
    }
    aggr2<<<nblk, 256>>>(att2, b2, out);
}

// round 8
// speedup vs baseline: 2.6381x; 1.0935x over previous
#include <cuda_runtime.h>
#include <cuda_bf16.h>
#include <cstdint>

#define NNODES 50000
#define NEDGES 800000
#define MPAD   50048      // 391 * 128
#define C1 256            // heads*hid layer1
#define C2 128            // out channels layer2
#define NEG_SLOPE 0.2f
#define EPS_DEN 1e-16f

// ---------------- scratch (device globals; no allocations allowed) ----------------
__device__ float g_xl1[NNODES * C1];
__device__ float g_xr1[NNODES * C1];
__device__ float g_hl2[NNODES * C2];
__device__ float g_hr2[NNODES * C2];
__device__ int   g_row[NNODES + 1];
__device__ int   g_cnt[NNODES];
__device__ int   g_srcs[NEDGES];
// bf16 split buffers
__device__ __align__(16) __nv_bfloat16 g_ah[MPAD * 256];
__device__ __align__(16) __nv_bfloat16 g_al[MPAD * 256];
__device__ __align__(16) __nv_bfloat16 g_bhL[32768];
__device__ __align__(16) __nv_bfloat16 g_blL[32768];
__device__ __align__(16) __nv_bfloat16 g_bhR[32768];
__device__ __align__(16) __nv_bfloat16 g_blR[32768];
__device__ __align__(16) __nv_bfloat16 g_bhL2[32768];
__device__ __align__(16) __nv_bfloat16 g_blL2[32768];
__device__ __align__(16) __nv_bfloat16 g_bhR2[32768];
__device__ __align__(16) __nv_bfloat16 g_blR2[32768];

// ---------------- helpers ----------------
__device__ __forceinline__ float lrelu(float x) { return x > 0.f ? x : NEG_SLOPE * x; }

__device__ __forceinline__ uint32_t smem_u32(const void* p) {
    uint32_t a;
    asm("{ .reg .u64 t; cvta.to.shared.u64 t, %1; cvt.u32.u64 %0, t; }" : "=r"(a) : "l"(p));
    return a;
}

__device__ __forceinline__ void ldsm_x4(uint32_t* r, uint32_t addr) {
    asm volatile("ldmatrix.sync.aligned.m8n8.x4.shared.b16 {%0,%1,%2,%3}, [%4];"
                 : "=r"(r[0]), "=r"(r[1]), "=r"(r[2]), "=r"(r[3]) : "r"(addr));
}

__device__ __forceinline__ void mma_bf16(float* c, const uint32_t* a,
                                         uint32_t b0, uint32_t b1) {
    asm volatile(
        "mma.sync.aligned.m16n8k16.row.col.f32.bf16.bf16.f32 "
        "{%0,%1,%2,%3}, {%4,%5,%6,%7}, {%8,%9}, {%0,%1,%2,%3};"
        : "+f"(c[0]), "+f"(c[1]), "+f"(c[2]), "+f"(c[3])
        : "r"(a[0]), "r"(a[1]), "r"(a[2]), "r"(a[3]), "r"(b0), "r"(b1));
}

// ---------------- CSR build ----------------
__global__ void k_zero() {
    int i = blockIdx.x * blockDim.x + threadIdx.x;
    if (i < NNODES) g_cnt[i] = 0;
}
__global__ void k_count(const int* __restrict__ ei) {
    int e = blockIdx.x * blockDim.x + threadIdx.x;
    if (e < NEDGES) atomicAdd(&g_cnt[ei[NEDGES + e]], 1);
}
__global__ __launch_bounds__(1024) void k_scan() {
    __shared__ int s[1024];
    __shared__ int carry_s;
    int t = threadIdx.x;
    if (t == 0) carry_s = 0;
    __syncthreads();
    for (int base = 0; base < NNODES; base += 4096) {
        int idx = base + t * 4;
        int v0 = (idx + 0 < NNODES) ? g_cnt[idx + 0] : 0;
        int v1 = (idx + 1 < NNODES) ? g_cnt[idx + 1] : 0;
        int v2 = (idx + 2 < NNODES) ? g_cnt[idx + 2] : 0;
        int v3 = (idx + 3 < NNODES) ? g_cnt[idx + 3] : 0;
        int tot = v0 + v1 + v2 + v3;
        s[t] = tot;
        __syncthreads();
        for (int off = 1; off < 1024; off <<= 1) {
            int x = (t >= off) ? s[t - off] : 0;
            __syncthreads();
            s[t] += x;
            __syncthreads();
        }
        int excl = carry_s + s[t] - tot;
        if (idx + 0 < NNODES) { g_row[idx + 0] = excl;                g_cnt[idx + 0] = 0; }
        if (idx + 1 < NNODES) { g_row[idx + 1] = excl + v0;           g_cnt[idx + 1] = 0; }
        if (idx + 2 < NNODES) { g_row[idx + 2] = excl + v0 + v1;      g_cnt[idx + 2] = 0; }
        if (idx + 3 < NNODES) { g_row[idx + 3] = excl + v0 + v1 + v2; g_cnt[idx + 3] = 0; }
        __syncthreads();
        if (t == 1023) carry_s += s[1023];
        __syncthreads();
    }
    if (t == 0) g_row[NNODES] = NEDGES;
}
__global__ void k_fill(const int* __restrict__ ei) {
    int e = blockIdx.x * blockDim.x + threadIdx.x;
    if (e >= NEDGES) return;
    int dst = ei[NEDGES + e];
    int pos = g_row[dst] + atomicAdd(&g_cnt[dst], 1);
    g_srcs[pos] = ei[e];
}

// ---------------- bf16 hi/lo splits ----------------
__global__ void k_split(const float* __restrict__ A, int M, int K) {
    int i = blockIdx.x * blockDim.x + threadIdx.x;
    if (i >= MPAD * K) return;
    int m = i / K;
    float v = (m < M) ? A[i] : 0.f;
    __nv_bfloat16 h = __float2bfloat16(v);
    g_ah[i] = h;
    g_al[i] = __float2bfloat16(v - __bfloat162float(h));
}
// W [K x Nn] fp32 -> bh/bl [Nn x K] bf16 (transposed)
__global__ void k_splitw(const float* __restrict__ W, __nv_bfloat16* __restrict__ bh,
                         __nv_bfloat16* __restrict__ bl, int K, int Nn) {
    int i = blockIdx.x * blockDim.x + threadIdx.x;
    if (i >= K * Nn) return;
    int k = i / Nn, n = i - k * Nn;
    float v = W[i];
    __nv_bfloat16 h = __float2bfloat16(v);
    bh[n * K + k] = h;
    bl[n * K + k] = __float2bfloat16(v - __bfloat162float(h));
}

// ---------------- warp-MMA bf16x3 GEMM --------------------------------------------
template <int KT, int NPER>
__global__ __launch_bounds__(256) void mgemm(
    const __nv_bfloat16* __restrict__ Ah, const __nv_bfloat16* __restrict__ Al,
    const __nv_bfloat16* __restrict__ Bh0, const __nv_bfloat16* __restrict__ Bl0,
    const __nv_bfloat16* __restrict__ Bh1, const __nv_bfloat16* __restrict__ Bl1,
    float* __restrict__ Cd0, float* __restrict__ Cd1) {
    constexpr int KCH = KT / 64;
    constexpr int NB  = NPER / 128;
    __shared__ __nv_bfloat16 As[128][72];
    __shared__ __nv_bfloat16 Bs[128][72];

    const int tid = threadIdx.x, wid = tid >> 5, lane = tid & 31;
    const int mat  = blockIdx.y / NB;
    const int ncol = (blockIdx.y % NB) * 128;
    const __nv_bfloat16* Bh = mat ? Bh1 : Bh0;
    const __nv_bfloat16* Bl = mat ? Bl1 : Bl0;
    float* Cd = mat ? Cd1 : Cd0;
    const size_t blockM = (size_t)blockIdx.x * 128;

    const int wm = wid >> 1, wn = wid & 1;
    float acc[2][8][4];
#pragma unroll
    for (int mi = 0; mi < 2; mi++)
#pragma unroll
        for (int ni = 0; ni < 8; ni++)
#pragma unroll
            for (int q = 0; q < 4; q++) acc[mi][ni][q] = 0.f;

    const int a_r = (lane & 7) + ((lane >> 3) & 1) * 8;
    const int a_c = (lane >> 4) * 8;
    const int b_r = (lane & 7) + (lane >> 4) * 8;
    const int b_c = ((lane >> 3) & 1) * 8;

    for (int c = 0; c < 3 * KCH; c++) {
        int seg = c / KCH;
        int kc = (c - seg * KCH) * 64;
        const __nv_bfloat16* Asrc = (seg == 2) ? Al : Ah;
        const __nv_bfloat16* Bsrc = (seg == 1) ? Bl : Bh;
#pragma unroll
        for (int u = tid; u < 1024; u += 256) {
            int r = u >> 3, j = u & 7;
            *(uint4*)((char*)&As[r][0] + j * 16) =
                *(const uint4*)(Asrc + (blockM + r) * KT + kc + j * 8);
            *(uint4*)((char*)&Bs[r][0] + j * 16) =
                *(const uint4*)(Bsrc + (size_t)(ncol + r) * KT + kc + j * 8);
        }
        __syncthreads();
#pragma unroll
        for (int ks = 0; ks < 4; ks++) {
            int k0 = ks * 16;
            uint32_t a[2][4];
#pragma unroll
            for (int mi = 0; mi < 2; mi++)
                ldsm_x4(a[mi], smem_u32(&As[wm * 32 + mi * 16 + a_r][k0 + a_c]));
            uint32_t b[4][4];
#pragma unroll
            for (int np = 0; np < 4; np++)
                ldsm_x4(b[np], smem_u32(&Bs[wn * 64 + np * 16 + b_r][k0 + b_c]));
#pragma unroll
            for (int mi = 0; mi < 2; mi++)
#pragma unroll
                for (int ni = 0; ni < 8; ni++)
                    mma_bf16(acc[mi][ni], a[mi],
                             b[ni >> 1][(ni & 1) * 2], b[ni >> 1][(ni & 1) * 2 + 1]);
        }
        __syncthreads();
    }

#pragma unroll
    for (int mi = 0; mi < 2; mi++) {
        int r0 = (int)blockM + wm * 32 + mi * 16 + (lane >> 2);
#pragma unroll
        for (int ni = 0; ni < 8; ni++) {
            int col = ncol + wn * 64 + ni * 8 + (lane & 3) * 2;
            if (r0 < NNODES)
                *(float2*)&Cd[(size_t)r0 * NPER + col] =
                    make_float2(acc[mi][ni][0], acc[mi][ni][1]);
            if (r0 + 8 < NNODES)
                *(float2*)&Cd[(size_t)(r0 + 8) * NPER + col] =
                    make_float2(acc[mi][ni][2], acc[mi][ni][3]);
        }
    }
}

// ---------------- layer 1 aggregation: half the heads per launch ----------------
// warp per node; lane covers 4 channels of [half*128, half*128+128).
// head = 2*half + (lane>>4); logit reduces over the 16-lane group.
// Epilogue: ELU(num/den + b1), written directly as bf16 hi/lo into g_ah/g_al.
__global__ __launch_bounds__(256) void aggr1h(const float* __restrict__ att,
                                              const float* __restrict__ b1,
                                              int half) {
    int node = blockIdx.x * 8 + (threadIdx.x >> 5);
    if (node >= NNODES) return;
    int lane = threadIdx.x & 31;
    int beg = g_row[node], end = g_row[node + 1];
    int ch = half * 128 + lane * 4;

    float4 r = *(const float4*)(g_xr1 + (size_t)node * C1 + ch);
    float4 t = *(const float4*)(att + ch);

    float4 acc = make_float4(0.f, 0.f, 0.f, 0.f);
    float den = 0.f;

    int i = beg;
    while (i < end) {
        int cnt = min(32, end - i);
        int mysrc = __ldg(&g_srcs[min(i + lane, end - 1)]);
        for (int j = 0; j < cnt; j++) {
            int s0 = __shfl_sync(0xffffffffu, mysrc, j);
            float4 a = __ldg((const float4*)(g_xl1 + (size_t)s0 * C1 + ch));
            float s = lrelu(a.x + r.x) * t.x + lrelu(a.y + r.y) * t.y +
                      lrelu(a.z + r.z) * t.z + lrelu(a.w + r.w) * t.w;
            s += __shfl_xor_sync(0xffffffffu, s, 1);
            s += __shfl_xor_sync(0xffffffffu, s, 2);
            s += __shfl_xor_sync(0xffffffffu, s, 4);
            s += __shfl_xor_sync(0xffffffffu, s, 8);
            float ee = __expf(s);
            acc.x = fmaf(ee, a.x, acc.x);
            acc.y = fmaf(ee, a.y, acc.y);
            acc.z = fmaf(ee, a.z, acc.z);
            acc.w = fmaf(ee, a.w, acc.w);
            den += ee;
        }
        i += cnt;
    }
    float inv = 1.f / (den + EPS_DEN);
    float4 bb = *(const float4*)(b1 + ch);
    float o[4];
    o[0] = acc.x * inv + bb.x;
    o[1] = acc.y * inv + bb.y;
    o[2] = acc.z * inv + bb.z;
    o[3] = acc.w * inv + bb.w;
#pragma unroll
    for (int q = 0; q < 4; q++) o[q] = o[q] > 0.f ? o[q] : expm1f(o[q]);
    // bf16 hi/lo split written directly (feeds layer-2 GEMM)
    __nv_bfloat16 hv[4], lv[4];
#pragma unroll
    for (int q = 0; q < 4; q++) {
        hv[q] = __float2bfloat16(o[q]);
        lv[q] = __float2bfloat16(o[q] - __bfloat162float(hv[q]));
    }
    *(uint64_t*)(g_ah + (size_t)node * 256 + ch) = *(const uint64_t*)hv;
    *(uint64_t*)(g_al + (size_t)node * 256 + ch) = *(const uint64_t*)lv;
}

// ---------------- layer 2 aggregation ----------------
__global__ __launch_bounds__(256) void aggr2(const float* __restrict__ att,
                                             const float* __restrict__ b2,
                                             float* __restrict__ out) {
    int node = blockIdx.x * 8 + (threadIdx.x >> 5);
    if (node >= NNODES) return;
    int lane = threadIdx.x & 31;
    int beg = g_row[node], end = g_row[node + 1];
    int base = lane * 4;

    float4 r = *(const float4*)(g_hr2 + (size_t)node * C2 + base);
    float4 t = *(const float4*)(att + base);

    float4 acc = make_float4(0.f, 0.f, 0.f, 0.f);
    float den = 0.f;

    int i = beg;
    while (i < end) {
        int cnt = min(32, end - i);
        int mysrc = __ldg(&g_srcs[min(i + lane, end - 1)]);
        for (int j = 0; j < cnt; j++) {
            int s0 = __shfl_sync(0xffffffffu, mysrc, j);
            float4 a = __ldg((const float4*)(g_hl2 + (size_t)s0 * C2 + base));
            float s = lrelu(a.x + r.x) * t.x + lrelu(a.y + r.y) * t.y +
                      lrelu(a.z + r.z) * t.z + lrelu(a.w + r.w) * t.w;
#pragma unroll
            for (int d = 16; d >= 1; d >>= 1)
                s += __shfl_xor_sync(0xffffffffu, s, d);
            float ee = __expf(s);
            acc.x = fmaf(ee, a.x, acc.x);
            acc.y = fmaf(ee, a.y, acc.y);
            acc.z = fmaf(ee, a.z, acc.z);
            acc.w = fmaf(ee, a.w, acc.w);
            den += ee;
        }
        i += cnt;
    }
    float inv = 1.f / (den + EPS_DEN);
    float4 bb = *(const float4*)(b2 + base);
    *(float4*)(out + (size_t)node * C2 + base) =
        make_float4(acc.x * inv + bb.x, acc.y * inv + bb.y,
                    acc.z * inv + bb.z, acc.w * inv + bb.w);
}

// ---------------- launch ----------------
extern "C" void kernel_launch(void* const* d_in, const int* in_sizes, int n_in,
                              void* d_out, int out_size) {
    const float* x    = (const float*)d_in[0];
    const int*   ei   = (const int*)d_in[1];
    const float* Wl1  = (const float*)d_in[2];
    const float* Wr1  = (const float*)d_in[3];
    const float* att1 = (const float*)d_in[4];
    const float* b1   = (const float*)d_in[5];
    const float* Wl2  = (const float*)d_in[6];
    const float* Wr2  = (const float*)d_in[7];
    const float* att2 = (const float*)d_in[8];
    const float* b2   = (const float*)d_in[9];
    float* out = (float*)d_out;

    float *xl1, *xr1, *hl2, *hr2;
    __nv_bfloat16 *ah, *al, *bhL, *blL, *bhR, *blR, *bhL2, *blL2, *bhR2, *blR2;
    cudaGetSymbolAddress((void**)&xl1, g_xl1);
    cudaGetSymbolAddress((void**)&xr1, g_xr1);
    cudaGetSymbolAddress((void**)&hl2, g_hl2);
    cudaGetSymbolAddress((void**)&hr2, g_hr2);
    cudaGetSymbolAddress((void**)&ah,  g_ah);
    cudaGetSymbolAddress((void**)&al,  g_al);
    cudaGetSymbolAddress((void**)&bhL, g_bhL);
    cudaGetSymbolAddress((void**)&blL, g_blL);
    cudaGetSymbolAddress((void**)&bhR, g_bhR);
    cudaGetSymbolAddress((void**)&blR, g_blR);
    cudaGetSymbolAddress((void**)&bhL2, g_bhL2);
    cudaGetSymbolAddress((void**)&blL2, g_blL2);
    cudaGetSymbolAddress((void**)&bhR2, g_bhR2);
    cudaGetSymbolAddress((void**)&blR2, g_blR2);

    const int T = 256;

    // side stream for CSR build (fork-join; capture-legal). Leaked handles are
    // host-side only — kernel_launch is invoked a bounded number of times.
    cudaStream_t s2;
    cudaStreamCreateWithFlags(&s2, cudaStreamNonBlocking);
    cudaEvent_t evF, evJ;
    cudaEventCreateWithFlags(&evF, cudaEventDisableTiming);
    cudaEventCreateWithFlags(&evJ, cudaEventDisableTiming);

    cudaEventRecord(evF, 0);
    cudaStreamWaitEvent(s2, evF, 0);
    // CSR build on side stream (depends only on ei)
    k_zero<<<(NNODES + T - 1) / T, T, 0, s2>>>();
    k_count<<<(NEDGES + T - 1) / T, T, 0, s2>>>(ei);
    k_scan<<<1, 1024, 0, s2>>>();
    k_fill<<<(NEDGES + T - 1) / T, T, 0, s2>>>(ei);
    cudaEventRecord(evJ, s2);

    // main stream: weight splits (all 4), input split, layer-1 dual GEMM
    k_splitw<<<(128 * 256 + T - 1) / T, T>>>(Wl1, bhL, blL, 128, 256);
    k_splitw<<<(128 * 256 + T - 1) / T, T>>>(Wr1, bhR, blR, 128, 256);
    k_splitw<<<(256 * 128 + T - 1) / T, T>>>(Wl2, bhL2, blL2, 256, 128);
    k_splitw<<<(256 * 128 + T - 1) / T, T>>>(Wr2, bhR2, blR2, 256, 128);
    k_split<<<(MPAD * 128 + T - 1) / T, T>>>(x, NNODES, 128);
    {
        dim3 grid(MPAD / 128, 4);
        mgemm<128, 256><<<grid, 256>>>(ah, al, bhL, blL, bhR, blR, xl1, xr1);
    }

    // join: aggregation needs CSR + GEMM outputs
    cudaStreamWaitEvent(0, evJ, 0);

    int nblk = (NNODES + 7) / 8;
    aggr1h<<<nblk, 256>>>(att1, b1, 0);   // heads 0,1 (L2-resident pass)
    aggr1h<<<nblk, 256>>>(att1, b1, 1);   // heads 2,3

    // layer 2 dual GEMM (consumes g_ah/g_al written by aggr1h)
    {
        dim3 grid(MPAD / 128, 2);
        mgemm<256, 128><<<grid, 256>>>(ah, al, bhL2, blL2, bhR2, blR2, hl2, hr2);
    }
    aggr2<<<nblk, 256>>>(att2, b2, out);
}

// round 9
// speedup vs baseline: 2.8290x; 1.0723x over previous
#include <cuda_runtime.h>
#include <cuda_bf16.h>
#include <cstdint>

#define NNODES 50000
#define NEDGES 800000
#define MPAD   50048      // 391 * 128
#define C1 256            // heads*hid layer1
#define C2 128            // out channels layer2
#define NEG_SLOPE 0.2f
#define EPS_DEN 1e-16f

// ---------------- scratch (device globals; no allocations allowed) ----------------
__device__ float g_xl1[NNODES * C1];
__device__ float g_xr1[NNODES * C1];
__device__ float g_hl2[NNODES * C2];
__device__ float g_hr2[NNODES * C2];
__device__ int   g_row[NNODES + 1];
__device__ int   g_cnt[NNODES];
__device__ int   g_srcs[NEDGES];
// bf16 split buffers
__device__ __align__(16) __nv_bfloat16 g_ah[MPAD * 256];
__device__ __align__(16) __nv_bfloat16 g_al[MPAD * 256];
__device__ __align__(16) __nv_bfloat16 g_bhL[32768];
__device__ __align__(16) __nv_bfloat16 g_blL[32768];
__device__ __align__(16) __nv_bfloat16 g_bhR[32768];
__device__ __align__(16) __nv_bfloat16 g_blR[32768];
__device__ __align__(16) __nv_bfloat16 g_bhL2[32768];
__device__ __align__(16) __nv_bfloat16 g_blL2[32768];
__device__ __align__(16) __nv_bfloat16 g_bhR2[32768];
__device__ __align__(16) __nv_bfloat16 g_blR2[32768];

// ---------------- helpers ----------------
__device__ __forceinline__ float lrelu(float x) { return x > 0.f ? x : NEG_SLOPE * x; }

__device__ __forceinline__ uint32_t smem_u32(const void* p) {
    uint32_t a;
    asm("{ .reg .u64 t; cvta.to.shared.u64 t, %1; cvt.u32.u64 %0, t; }" : "=r"(a) : "l"(p));
    return a;
}

__device__ __forceinline__ void ldsm_x4(uint32_t* r, uint32_t addr) {
    asm volatile("ldmatrix.sync.aligned.m8n8.x4.shared.b16 {%0,%1,%2,%3}, [%4];"
                 : "=r"(r[0]), "=r"(r[1]), "=r"(r[2]), "=r"(r[3]) : "r"(addr));
}

__device__ __forceinline__ void mma_bf16(float* c, const uint32_t* a,
                                         uint32_t b0, uint32_t b1) {
    asm volatile(
        "mma.sync.aligned.m16n8k16.row.col.f32.bf16.bf16.f32 "
        "{%0,%1,%2,%3}, {%4,%5,%6,%7}, {%8,%9}, {%0,%1,%2,%3};"
        : "+f"(c[0]), "+f"(c[1]), "+f"(c[2]), "+f"(c[3])
        : "r"(a[0]), "r"(a[1]), "r"(a[2]), "r"(a[3]), "r"(b0), "r"(b1));
}

#define CP_ASYNC16(dst, src) \
    asm volatile("cp.async.cg.shared.global [%0], [%1], 16;" :: "r"(dst), "l"(src))
#define CP_COMMIT() asm volatile("cp.async.commit_group;")
#define CP_WAIT1()  asm volatile("cp.async.wait_group 1;")
#define CP_WAIT0()  asm volatile("cp.async.wait_group 0;")

// ---------------- CSR build ----------------
__global__ void k_zero() {
    int i = blockIdx.x * blockDim.x + threadIdx.x;
    if (i < NNODES) g_cnt[i] = 0;
}
__global__ void k_count(const int* __restrict__ ei) {
    int e = blockIdx.x * blockDim.x + threadIdx.x;
    if (e < NEDGES) atomicAdd(&g_cnt[ei[NEDGES + e]], 1);
}
__global__ __launch_bounds__(1024) void k_scan() {
    __shared__ int s[1024];
    __shared__ int carry_s;
    int t = threadIdx.x;
    if (t == 0) carry_s = 0;
    __syncthreads();
    for (int base = 0; base < NNODES; base += 4096) {
        int idx = base + t * 4;
        int v0 = (idx + 0 < NNODES) ? g_cnt[idx + 0] : 0;
        int v1 = (idx + 1 < NNODES) ? g_cnt[idx + 1] : 0;
        int v2 = (idx + 2 < NNODES) ? g_cnt[idx + 2] : 0;
        int v3 = (idx + 3 < NNODES) ? g_cnt[idx + 3] : 0;
        int tot = v0 + v1 + v2 + v3;
        s[t] = tot;
        __syncthreads();
        for (int off = 1; off < 1024; off <<= 1) {
            int x = (t >= off) ? s[t - off] : 0;
            __syncthreads();
            s[t] += x;
            __syncthreads();
        }
        int excl = carry_s + s[t] - tot;
        if (idx + 0 < NNODES) { g_row[idx + 0] = excl;                g_cnt[idx + 0] = 0; }
        if (idx + 1 < NNODES) { g_row[idx + 1] = excl + v0;           g_cnt[idx + 1] = 0; }
        if (idx + 2 < NNODES) { g_row[idx + 2] = excl + v0 + v1;      g_cnt[idx + 2] = 0; }
        if (idx + 3 < NNODES) { g_row[idx + 3] = excl + v0 + v1 + v2; g_cnt[idx + 3] = 0; }
        __syncthreads();
        if (t == 1023) carry_s += s[1023];
        __syncthreads();
    }
    if (t == 0) g_row[NNODES] = NEDGES;
}
__global__ void k_fill(const int* __restrict__ ei) {
    int e = blockIdx.x * blockDim.x + threadIdx.x;
    if (e >= NEDGES) return;
    int dst = ei[NEDGES + e];
    int pos = g_row[dst] + atomicAdd(&g_cnt[dst], 1);
    g_srcs[pos] = ei[e];
}

// ---------------- bf16 hi/lo splits ----------------
__global__ void k_split(const float* __restrict__ A, int M, int K) {
    int i = blockIdx.x * blockDim.x + threadIdx.x;
    if (i >= MPAD * K) return;
    int m = i / K;
    float v = (m < M) ? A[i] : 0.f;
    __nv_bfloat16 h = __float2bfloat16(v);
    g_ah[i] = h;
    g_al[i] = __float2bfloat16(v - __bfloat162float(h));
}
// W [K x Nn] fp32 -> bh/bl [Nn x K] bf16 (transposed)
__global__ void k_splitw(const float* __restrict__ W, __nv_bfloat16* __restrict__ bh,
                         __nv_bfloat16* __restrict__ bl, int K, int Nn) {
    int i = blockIdx.x * blockDim.x + threadIdx.x;
    if (i >= K * Nn) return;
    int k = i / Nn, n = i - k * Nn;
    float v = W[i];
    __nv_bfloat16 h = __float2bfloat16(v);
    bh[n * K + k] = h;
    bl[n * K + k] = __float2bfloat16(v - __bfloat162float(h));
}

// ---------------- warp-MMA bf16x3 GEMM, cp.async double-buffered ------------------
// stage layout (bytes): A at s*36864, B at s*36864+18432; row pitch 144 B.
template <int KT, int NPER>
__global__ __launch_bounds__(256) void mgemm(
    const __nv_bfloat16* __restrict__ Ah, const __nv_bfloat16* __restrict__ Al,
    const __nv_bfloat16* __restrict__ Bh0, const __nv_bfloat16* __restrict__ Bl0,
    const __nv_bfloat16* __restrict__ Bh1, const __nv_bfloat16* __restrict__ Bl1,
    float* __restrict__ Cd0, float* __restrict__ Cd1) {
    constexpr int KCH = KT / 64;
    constexpr int NCH = 3 * KCH;
    constexpr int NB  = NPER / 128;
    extern __shared__ char dsm[];

    const int tid = threadIdx.x, wid = tid >> 5, lane = tid & 31;
    const int mat  = blockIdx.y / NB;
    const int ncol = (blockIdx.y % NB) * 128;
    const __nv_bfloat16* Bh = mat ? Bh1 : Bh0;
    const __nv_bfloat16* Bl = mat ? Bl1 : Bl0;
    float* Cd = mat ? Cd1 : Cd0;
    const size_t blockM = (size_t)blockIdx.x * 128;

    const int wm = wid >> 1, wn = wid & 1;
    float acc[2][8][4];
#pragma unroll
    for (int mi = 0; mi < 2; mi++)
#pragma unroll
        for (int ni = 0; ni < 8; ni++)
#pragma unroll
            for (int q = 0; q < 4; q++) acc[mi][ni][q] = 0.f;

    const int a_r = (lane & 7) + ((lane >> 3) & 1) * 8;
    const int a_c = (lane >> 4) * 8;
    const int b_r = (lane & 7) + (lane >> 4) * 8;
    const int b_c = ((lane >> 3) & 1) * 8;

    auto issue = [&](int c, int s) {
        int seg = c / KCH;
        int kc = (c - seg * KCH) * 64;
        const __nv_bfloat16* Asrc = (seg == 2) ? Al : Ah;
        const __nv_bfloat16* Bsrc = (seg == 1) ? Bl : Bh;
        char* abase = dsm + s * 36864;
        char* bbase = abase + 18432;
#pragma unroll
        for (int u = tid; u < 1024; u += 256) {
            int r = u >> 3, j = u & 7;
            CP_ASYNC16(smem_u32(abase + r * 144 + j * 16),
                       Asrc + (blockM + r) * KT + kc + j * 8);
            CP_ASYNC16(smem_u32(bbase + r * 144 + j * 16),
                       Bsrc + (size_t)(ncol + r) * KT + kc + j * 8);
        }
        CP_COMMIT();
    };

    issue(0, 0);
    for (int c = 0; c < NCH; c++) {
        if (c + 1 < NCH) { issue(c + 1, (c + 1) & 1); CP_WAIT1(); }
        else             { CP_WAIT0(); }
        __syncthreads();
        char* abase = dsm + (c & 1) * 36864;
        char* bbase = abase + 18432;
#pragma unroll
        for (int ks = 0; ks < 4; ks++) {
            int k0 = ks * 16;
            uint32_t a[2][4];
#pragma unroll
            for (int mi = 0; mi < 2; mi++)
                ldsm_x4(a[mi], smem_u32(abase + (wm * 32 + mi * 16 + a_r) * 144 +
                                        (k0 + a_c) * 2));
            uint32_t b[4][4];
#pragma unroll
            for (int np = 0; np < 4; np++)
                ldsm_x4(b[np], smem_u32(bbase + (wn * 64 + np * 16 + b_r) * 144 +
                                        (k0 + b_c) * 2));
#pragma unroll
            for (int mi = 0; mi < 2; mi++)
#pragma unroll
                for (int ni = 0; ni < 8; ni++)
                    mma_bf16(acc[mi][ni], a[mi],
                             b[ni >> 1][(ni & 1) * 2], b[ni >> 1][(ni & 1) * 2 + 1]);
        }
        __syncthreads();
    }

#pragma unroll
    for (int mi = 0; mi < 2; mi++) {
        int r0 = (int)blockM + wm * 32 + mi * 16 + (lane >> 2);
#pragma unroll
        for (int ni = 0; ni < 8; ni++) {
            int col = ncol + wn * 64 + ni * 8 + (lane & 3) * 2;
            if (r0 < NNODES)
                *(float2*)&Cd[(size_t)r0 * NPER + col] =
                    make_float2(acc[mi][ni][0], acc[mi][ni][1]);
            if (r0 + 8 < NNODES)
                *(float2*)&Cd[(size_t)(r0 + 8) * NPER + col] =
                    make_float2(acc[mi][ni][2], acc[mi][ni][3]);
        }
    }
}

// ---------------- layer 1 aggregation: half heads, 2 edges/warp-iter --------------
// warp per node; lane = g*16 + gl; group g handles edge pair member g.
// gl covers 8 channels of [half*128, half*128+128); head = subgroup of 8 lanes.
// logit reduce: xor 1,2,4 (64 ch per head); group combine at end via xor 16.
__global__ __launch_bounds__(256) void aggr1h(const float* __restrict__ att,
                                              const float* __restrict__ b1,
                                              int half) {
    int node = blockIdx.x * 8 + (threadIdx.x >> 5);
    if (node >= NNODES) return;
    int lane = threadIdx.x & 31;
    int g  = lane >> 4;
    int gl = lane & 15;
    int beg = g_row[node], end = g_row[node + 1];
    int ch = half * 128 + gl * 8;

    const float4* pr = (const float4*)(g_xr1 + (size_t)node * C1 + ch);
    float4 r0 = pr[0], r1 = pr[1];
    const float4* pa = (const float4*)(att + ch);
    float4 t0 = pa[0], t1 = pa[1];

    float acc[8];
#pragma unroll
    for (int q = 0; q < 8; q++) acc[q] = 0.f;
    float den = 0.f;

    int i = beg;
    while (i < end) {
        int cnt = min(32, end - i);
        int mysrc = __ldg(&g_srcs[i + min(lane, cnt - 1)]);
        for (int jb = 0; jb < cnt; jb += 2) {
            int idx = min(jb + g, cnt - 1);
            int src = __shfl_sync(0xffffffffu, mysrc, idx);
            bool valid = (jb + g) < cnt;
            const float4* pl = (const float4*)(g_xl1 + (size_t)src * C1 + ch);
            float4 a0 = __ldg(pl), a1 = __ldg(pl + 1);
            float s = lrelu(a0.x + r0.x) * t0.x + lrelu(a0.y + r0.y) * t0.y +
                      lrelu(a0.z + r0.z) * t0.z + lrelu(a0.w + r0.w) * t0.w +
                      lrelu(a1.x + r1.x) * t1.x + lrelu(a1.y + r1.y) * t1.y +
                      lrelu(a1.z + r1.z) * t1.z + lrelu(a1.w + r1.w) * t1.w;
            s += __shfl_xor_sync(0xffffffffu, s, 1);
            s += __shfl_xor_sync(0xffffffffu, s, 2);
            s += __shfl_xor_sync(0xffffffffu, s, 4);
            float ee = valid ? __expf(s) : 0.f;
            acc[0] = fmaf(ee, a0.x, acc[0]);
            acc[1] = fmaf(ee, a0.y, acc[1]);
            acc[2] = fmaf(ee, a0.z, acc[2]);
            acc[3] = fmaf(ee, a0.w, acc[3]);
            acc[4] = fmaf(ee, a1.x, acc[4]);
            acc[5] = fmaf(ee, a1.y, acc[5]);
            acc[6] = fmaf(ee, a1.z, acc[6]);
            acc[7] = fmaf(ee, a1.w, acc[7]);
            den += ee;
        }
        i += cnt;
    }
    // combine edge groups (same channels / same head across xor 16)
#pragma unroll
    for (int q = 0; q < 8; q++) acc[q] += __shfl_xor_sync(0xffffffffu, acc[q], 16);
    den += __shfl_xor_sync(0xffffffffu, den, 16);

    if (g == 0) {
        float inv = 1.f / (den + EPS_DEN);
        const float4* pb = (const float4*)(b1 + ch);
        float4 bb0 = pb[0], bb1 = pb[1];
        float o[8];
        o[0] = acc[0] * inv + bb0.x;  o[1] = acc[1] * inv + bb0.y;
        o[2] = acc[2] * inv + bb0.z;  o[3] = acc[3] * inv + bb0.w;
        o[4] = acc[4] * inv + bb1.x;  o[5] = acc[5] * inv + bb1.y;
        o[6] = acc[6] * inv + bb1.z;  o[7] = acc[7] * inv + bb1.w;
#pragma unroll
        for (int q = 0; q < 8; q++) o[q] = o[q] > 0.f ? o[q] : expm1f(o[q]);
        __nv_bfloat16 hv[8], lv[8];
#pragma unroll
        for (int q = 0; q < 8; q++) {
            hv[q] = __float2bfloat16(o[q]);
            lv[q] = __float2bfloat16(o[q] - __bfloat162float(hv[q]));
        }
        *(uint4*)(g_ah + (size_t)node * 256 + ch) = *(const uint4*)hv;
        *(uint4*)(g_al + (size_t)node * 256 + ch) = *(const uint4*)lv;
    }
}

// ---------------- layer 2 aggregation: 2 edges/warp-iter ----------------
__global__ __launch_bounds__(256) void aggr2(const float* __restrict__ att,
                                             const float* __restrict__ b2,
                                             float* __restrict__ out) {
    int node = blockIdx.x * 8 + (threadIdx.x >> 5);
    if (node >= NNODES) return;
    int lane = threadIdx.x & 31;
    int g  = lane >> 4;
    int gl = lane & 15;
    int beg = g_row[node], end = g_row[node + 1];
    int ch = gl * 8;

    const float4* pr = (const float4*)(g_hr2 + (size_t)node * C2 + ch);
    float4 r0 = pr[0], r1 = pr[1];
    const float4* pa = (const float4*)(att + ch);
    float4 t0 = pa[0], t1 = pa[1];

    float acc[8];
#pragma unroll
    for (int q = 0; q < 8; q++) acc[q] = 0.f;
    float den = 0.f;

    int i = beg;
    while (i < end) {
        int cnt = min(32, end - i);
        int mysrc = __ldg(&g_srcs[i + min(lane, cnt - 1)]);
        for (int jb = 0; jb < cnt; jb += 2) {
            int idx = min(jb + g, cnt - 1);
            int src = __shfl_sync(0xffffffffu, mysrc, idx);
            bool valid = (jb + g) < cnt;
            const float4* pl = (const float4*)(g_hl2 + (size_t)src * C2 + ch);
            float4 a0 = __ldg(pl), a1 = __ldg(pl + 1);
            float s = lrelu(a0.x + r0.x) * t0.x + lrelu(a0.y + r0.y) * t0.y +
                      lrelu(a0.z + r0.z) * t0.z + lrelu(a0.w + r0.w) * t0.w +
                      lrelu(a1.x + r1.x) * t1.x + lrelu(a1.y + r1.y) * t1.y +
                      lrelu(a1.z + r1.z) * t1.z + lrelu(a1.w + r1.w) * t1.w;
            s += __shfl_xor_sync(0xffffffffu, s, 1);
            s += __shfl_xor_sync(0xffffffffu, s, 2);
            s += __shfl_xor_sync(0xffffffffu, s, 4);
            s += __shfl_xor_sync(0xffffffffu, s, 8);
            float ee = valid ? __expf(s) : 0.f;
            acc[0] = fmaf(ee, a0.x, acc[0]);
            acc[1] = fmaf(ee, a0.y, acc[1]);
            acc[2] = fmaf(ee, a0.z, acc[2]);
            acc[3] = fmaf(ee, a0.w, acc[3]);
            acc[4] = fmaf(ee, a1.x, acc[4]);
            acc[5] = fmaf(ee, a1.y, acc[5]);
            acc[6] = fmaf(ee, a1.z, acc[6]);
            acc[7] = fmaf(ee, a1.w, acc[7]);
            den += ee;
        }
        i += cnt;
    }
#pragma unroll
    for (int q = 0; q < 8; q++) acc[q] += __shfl_xor_sync(0xffffffffu, acc[q], 16);
    den += __shfl_xor_sync(0xffffffffu, den, 16);

    if (g == 0) {
        float inv = 1.f / (den + EPS_DEN);
        const float4* pb = (const float4*)(b2 + ch);
        float4 bb0 = pb[0], bb1 = pb[1];
        float4* po = (float4*)(out + (size_t)node * C2 + ch);
        po[0] = make_float4(acc[0] * inv + bb0.x, acc[1] * inv + bb0.y,
                            acc[2] * inv + bb0.z, acc[3] * inv + bb0.w);
        po[1] = make_float4(acc[4] * inv + bb1.x, acc[5] * inv + bb1.y,
                            acc[6] * inv + bb1.z, acc[7] * inv + bb1.w);
    }
}

// ---------------- launch ----------------
extern "C" void kernel_launch(void* const* d_in, const int* in_sizes, int n_in,
                              void* d_out, int out_size) {
    const float* x    = (const float*)d_in[0];
    const int*   ei   = (const int*)d_in[1];
    const float* Wl1  = (const float*)d_in[2];
    const float* Wr1  = (const float*)d_in[3];
    const float* att1 = (const float*)d_in[4];
    const float* b1   = (const float*)d_in[5];
    const float* Wl2  = (const float*)d_in[6];
    const float* Wr2  = (const float*)d_in[7];
    const float* att2 = (const float*)d_in[8];
    const float* b2   = (const float*)d_in[9];
    float* out = (float*)d_out;

    float *xl1, *xr1, *hl2, *hr2;
    __nv_bfloat16 *ah, *al, *bhL, *blL, *bhR, *blR, *bhL2, *blL2, *bhR2, *blR2;
    cudaGetSymbolAddress((void**)&xl1, g_xl1);
    cudaGetSymbolAddress((void**)&xr1, g_xr1);
    cudaGetSymbolAddress((void**)&hl2, g_hl2);
    cudaGetSymbolAddress((void**)&hr2, g_hr2);
    cudaGetSymbolAddress((void**)&ah,  g_ah);
    cudaGetSymbolAddress((void**)&al,  g_al);
    cudaGetSymbolAddress((void**)&bhL, g_bhL);
    cudaGetSymbolAddress((void**)&blL, g_blL);
    cudaGetSymbolAddress((void**)&bhR, g_bhR);
    cudaGetSymbolAddress((void**)&blR, g_blR);
    cudaGetSymbolAddress((void**)&bhL2, g_bhL2);
    cudaGetSymbolAddress((void**)&blL2, g_blL2);
    cudaGetSymbolAddress((void**)&bhR2, g_bhR2);
    cudaGetSymbolAddress((void**)&blR2, g_blR2);

    const int T = 256;
    const int DSMEM = 73728;
    cudaFuncSetAttribute((const void*)mgemm<128, 256>,
                         cudaFuncAttributeMaxDynamicSharedMemorySize, DSMEM);
    cudaFuncSetAttribute((const void*)mgemm<256, 128>,
                         cudaFuncAttributeMaxDynamicSharedMemorySize, DSMEM);

    // side stream for CSR build (fork-join; capture-legal).
    cudaStream_t s2;
    cudaStreamCreateWithFlags(&s2, cudaStreamNonBlocking);
    cudaEvent_t evF, evJ;
    cudaEventCreateWithFlags(&evF, cudaEventDisableTiming);
    cudaEventCreateWithFlags(&evJ, cudaEventDisableTiming);

    cudaEventRecord(evF, 0);
    cudaStreamWaitEvent(s2, evF, 0);
    k_zero<<<(NNODES + T - 1) / T, T, 0, s2>>>();
    k_count<<<(NEDGES + T - 1) / T, T, 0, s2>>>(ei);
    k_scan<<<1, 1024, 0, s2>>>();
    k_fill<<<(NEDGES + T - 1) / T, T, 0, s2>>>(ei);
    cudaEventRecord(evJ, s2);

    // main stream: weight splits (all 4), input split, layer-1 dual GEMM
    k_splitw<<<(128 * 256 + T - 1) / T, T>>>(Wl1, bhL, blL, 128, 256);
    k_splitw<<<(128 * 256 + T - 1) / T, T>>>(Wr1, bhR, blR, 128, 256);
    k_splitw<<<(256 * 128 + T - 1) / T, T>>>(Wl2, bhL2, blL2, 256, 128);
    k_splitw<<<(256 * 128 + T - 1) / T, T>>>(Wr2, bhR2, blR2, 256, 128);
    k_split<<<(MPAD * 128 + T - 1) / T, T>>>(x, NNODES, 128);
    {
        dim3 grid(MPAD / 128, 4);
        mgemm<128, 256><<<grid, 256, DSMEM>>>(ah, al, bhL, blL, bhR, blR, xl1, xr1);
    }

    // join: aggregation needs CSR + GEMM outputs
    cudaStreamWaitEvent(0, evJ, 0);

    int nblk = (NNODES + 7) / 8;
    aggr1h<<<nblk, 256>>>(att1, b1, 0);   // heads 0,1 (L2-resident pass)
    aggr1h<<<nblk, 256>>>(att1, b1, 1);   // heads 2,3

    // layer 2 dual GEMM (consumes g_ah/g_al written by aggr1h)
    {
        dim3 grid(MPAD / 128, 2);
        mgemm<256, 128><<<grid, 256, DSMEM>>>(ah, al, bhL2, blL2, bhR2, blR2, hl2, hr2);
    }
    aggr2<<<nblk, 256>>>(att2, b2, out);
}